// round 8
// baseline (speedup 1.0000x reference)
#include <cuda_runtime.h>
#include <cuda_bf16.h>
#include <math.h>
#include <stdint.h>

// ---------------- model constants ----------------
#define BDIM   8
#define TTXT   64
#define TSEQ   256
#define TTOT   320
#define MROWS  (BDIM*TTOT)    // 2560
#define DIM    1024
#define LDIMC  128
#define FFN    4096
#define HEADS  16
#define HDIM   64
#define NLAYER 4
#define HID    1024
#define KF1    1154
#define KP1    1160
#define NSTEPS 16

// ---------------- scratch ----------------
__device__ __align__(16) uint16_t g_seqb[BDIM*TSEQ*LDIMC];
__device__ __align__(16) float    g_x   [BDIM*TSEQ*DIM];
__device__ __align__(16) float    g_h   [MROWS*DIM];
__device__ __align__(16) uint16_t g_tmpb[MROWS*DIM];
__device__ __align__(16) float    g_qkv [MROWS*3*DIM];
__device__ __align__(16) uint16_t g_attb[MROWS*DIM];
__device__ __align__(16) uint16_t g_midb[MROWS*FFN];
__device__ __align__(16) float    g_last[BDIM*DIM];
__device__ __align__(16) float    g_cur [BDIM*LDIMC];
__device__ __align__(16) float    g_f1  [BDIM*HID];
__device__ __align__(16) float    g_f2  [BDIM*HID];
__device__ __align__(16) float    g_p01 [2*MROWS*DIM];
// bf16 transposed weights  W^T [N][K]
__device__ __align__(16) uint16_t g_wint [DIM*LDIMC];
__device__ __align__(16) uint16_t g_wqkvt[NLAYER*3*DIM*DIM];
__device__ __align__(16) uint16_t g_wot  [NLAYER*DIM*DIM];
__device__ __align__(16) uint16_t g_w1t  [NLAYER*FFN*DIM];
__device__ __align__(16) uint16_t g_w2t  [NLAYER*DIM*FFN];
// fp32 transposed flow weights
__device__ __align__(16) float g_wf1t[HID*KP1];
__device__ __align__(16) float g_wf2t[HID*HID];
__device__ __align__(16) float g_wf3t[LDIMC*HID];
// grid barrier state
__device__ unsigned g_bar_cnt = 0;
__device__ unsigned g_bar_gen = 0;

// ---------------- helpers ----------------
__device__ __forceinline__ float gelu_tanh(float x) {
    const float c = 0.7978845608028654f;
    float t = c * (x + 0.044715f * x * x * x);
    return 0.5f * x * (1.0f + tanhf(t));
}
__device__ __forceinline__ float silu(float x) { return x / (1.0f + __expf(-x)); }
__device__ __forceinline__ uint32_t pack_bf2(float a, float b) {
    __nv_bfloat162 h2 = __floats2bfloat162_rn(a, b);
    return *(uint32_t*)&h2;
}
__device__ __forceinline__ uint16_t bf16u(float a) {
    __nv_bfloat16 h = __float2bfloat16_rn(a);
    return *(uint16_t*)&h;
}
__device__ __forceinline__ void cp_async16(void* smem_dst, const void* gmem_src) {
    uint32_t s = (uint32_t)__cvta_generic_to_shared(smem_dst);
    asm volatile("cp.async.cg.shared.global [%0], [%1], 16;\n" :: "r"(s), "l"(gmem_src));
}
__device__ __forceinline__ int swz(int c) { return c + (c >> 4); }
#define LDSM_X4(r0, r1, r2, r3, addr) \
    asm volatile("ldmatrix.sync.aligned.m8n8.x4.shared.b16 {%0,%1,%2,%3}, [%4];" \
                 : "=r"(r0), "=r"(r1), "=r"(r2), "=r"(r3) : "r"(addr))

// ---------------- prep kernels ----------------
// dst[z][n][k] (bf16) = src[z][k][n] (fp32)
__global__ void tconv_kernel(const float* __restrict__ src, uint16_t* __restrict__ dst,
                             int K, int N) {
    __shared__ float tile[32][65];
    const float* s = src + (size_t)blockIdx.z * K * N;
    uint16_t* d    = dst + (size_t)blockIdx.z * K * N;
    int k0 = blockIdx.y * 64, n0 = blockIdx.x * 32;
    int tx = threadIdx.x, ty = threadIdx.y;
    #pragma unroll
    for (int i = 0; i < 8; i++) {
        int kk = ty + i * 8;
        tile[tx][kk] = s[(size_t)(k0 + kk) * N + n0 + tx];
    }
    __syncthreads();
    #pragma unroll
    for (int i = 0; i < 4; i++) {
        int nn = ty + i * 8;
        uint32_t p = pack_bf2(tile[nn][2 * tx], tile[nn][2 * tx + 1]);
        *(uint32_t*)&d[(size_t)(n0 + nn) * K + k0 + 2 * tx] = p;
    }
}
__global__ void zero_kernel(float* __restrict__ p, int n) {
    int i = blockIdx.x * blockDim.x + threadIdx.x;
    if (i < n) p[i] = 0.f;
}
__global__ void transpose_kernel(const float* __restrict__ src, float* __restrict__ dst,
                                 int R, int C, int dstride) {
    __shared__ float tile[32][33];
    int c0 = blockIdx.x * 32, r0 = blockIdx.y * 32;
    int tx = threadIdx.x, ty = threadIdx.y;
    #pragma unroll
    for (int i = 0; i < 4; i++) {
        int rr = r0 + ty + i * 8, cc = c0 + tx;
        if (rr < R && cc < C) tile[ty + i * 8][tx] = src[(size_t)rr * C + cc];
    }
    __syncthreads();
    #pragma unroll
    for (int i = 0; i < 4; i++) {
        int cc = c0 + ty + i * 8, rr = r0 + tx;
        if (cc < C && rr < R) dst[(size_t)cc * dstride + rr] = tile[tx][ty + i * 8];
    }
}

__global__ void nanfix_kernel(const float* __restrict__ seq,
                              const float* __restrict__ bos,
                              uint16_t* __restrict__ out, int n) {
    int i = blockIdx.x * blockDim.x + threadIdx.x;
    if (i < n) {
        float v = seq[i];
        v = (v != v) ? bos[i & (LDIMC - 1)] : v;
        out[i] = bf16u(v);
    }
}

// ---------------- fused concat + LayerNorm (fp32 h out + bf16 LN out) ----------------
__global__ void __launch_bounds__(256) concat_ln_kernel(
        const float* __restrict__ text, const float* __restrict__ x,
        float* __restrict__ h, uint16_t* __restrict__ lnout,
        const float* __restrict__ g, const float* __restrict__ bta) {
    int row = blockIdx.x, tid = threadIdx.x;
    int b = row / TTOT, t = row - b * TTOT;
    float4 v;
    if (t < TTXT)
        v = ((const float4*)text)[(size_t)(b * TTXT + t) * 256 + tid];
    else
        v = ((const float4*)x)[(size_t)(b * TSEQ + (t - TTXT)) * 256 + tid];
    ((float4*)(h + (size_t)row * DIM))[tid] = v;

    float s  = v.x + v.y + v.z + v.w;
    float ss = v.x*v.x + v.y*v.y + v.z*v.z + v.w*v.w;
    #pragma unroll
    for (int o = 16; o; o >>= 1) {
        s  += __shfl_xor_sync(0xffffffffu, s,  o);
        ss += __shfl_xor_sync(0xffffffffu, ss, o);
    }
    __shared__ float sh[16];
    int w = tid >> 5, l = tid & 31;
    if (l == 0) { sh[w] = s; sh[8 + w] = ss; }
    __syncthreads();
    float S = 0.f, SS = 0.f;
    #pragma unroll
    for (int i = 0; i < 8; i++) { S += sh[i]; SS += sh[8 + i]; }
    float mean = S * (1.0f / DIM);
    float var  = SS * (1.0f / DIM) - mean * mean;
    float rs   = rsqrtf(var + 1e-5f);
    float4 gg = ((const float4*)g)[tid];
    float4 bb = ((const float4*)bta)[tid];
    uint2 o2;
    o2.x = pack_bf2((v.x - mean) * rs * gg.x + bb.x, (v.y - mean) * rs * gg.y + bb.y);
    o2.y = pack_bf2((v.z - mean) * rs * gg.z + bb.z, (v.w - mean) * rs * gg.w + bb.w);
    ((uint2*)(lnout + (size_t)row * DIM))[tid] = o2;
}

// ---------------- combine split-K partials + optional fused LN ----------------
__global__ void __launch_bounds__(256) combine_ln_kernel(
        const float* __restrict__ p0, const float* __restrict__ p1,
        const float* __restrict__ bias, float* __restrict__ h,
        const float* __restrict__ g, const float* __restrict__ bta,
        uint16_t* __restrict__ lnout, int do_ln) {
    int row = blockIdx.x, tid = threadIdx.x;
    size_t off = (size_t)row * DIM;
    float4 a  = ((const float4*)(p0 + off))[tid];
    float4 b4 = ((const float4*)(p1 + off))[tid];
    float4 r  = ((const float4*)(h + off))[tid];
    float4 bb = ((const float4*)bias)[tid];
    r.x += a.x + b4.x + bb.x;
    r.y += a.y + b4.y + bb.y;
    r.z += a.z + b4.z + bb.z;
    r.w += a.w + b4.w + bb.w;
    ((float4*)(h + off))[tid] = r;
    if (!do_ln) return;
    float s  = r.x + r.y + r.z + r.w;
    float ss = r.x*r.x + r.y*r.y + r.z*r.z + r.w*r.w;
    #pragma unroll
    for (int o = 16; o; o >>= 1) {
        s  += __shfl_xor_sync(0xffffffffu, s,  o);
        ss += __shfl_xor_sync(0xffffffffu, ss, o);
    }
    __shared__ float sh[16];
    int w = tid >> 5, l = tid & 31;
    if (l == 0) { sh[w] = s; sh[8 + w] = ss; }
    __syncthreads();
    float S = 0.f, SS = 0.f;
    #pragma unroll
    for (int i = 0; i < 8; i++) { S += sh[i]; SS += sh[8 + i]; }
    float mean = S * (1.0f / DIM);
    float var  = SS * (1.0f / DIM) - mean * mean;
    float rs   = rsqrtf(var + 1e-5f);
    float4 gg = ((const float4*)g)[tid];
    float4 b2 = ((const float4*)bta)[tid];
    uint2 o2;
    o2.x = pack_bf2((r.x - mean) * rs * gg.x + b2.x, (r.y - mean) * rs * gg.y + b2.y);
    o2.y = pack_bf2((r.z - mean) * rs * gg.z + b2.z, (r.w - mean) * rs * gg.w + b2.w);
    ((uint2*)(lnout + off))[tid] = o2;
}

// ---------------- bf16 tensor-core GEMM (mma.sync + ldmatrix, 3-stage cp.async) ----------------
// C[m][n] = epi( sum_k A[m][k]*Bt[n][k] + bias )
// A bf16 row-major [M][lda]; Bt bf16 [N][ldb] (W transposed)
// epi: 0 = bias->Cf ; 1 = bias+gelu->Cb(bf16) ; 3 = raw partial -> Cf + z*M*N
#define BKT 64
#define ASTR 72                       // bf16 elems per smem row
#define ATILE (128*ASTR)              // elems per operand per stage
#define TGSTAGES 3
#define STAGE_ELEMS (2*ATILE)
#define STAGE_BYTES (STAGE_ELEMS*2)
#define TG_SMEM (TGSTAGES*STAGE_BYTES)     // 110592 bytes

__global__ void __launch_bounds__(256, 2) tgemm_bf16(
        const uint16_t* __restrict__ A, int lda,
        const uint16_t* __restrict__ Bt, int ldb,
        const float* __restrict__ bias,
        float* __restrict__ Cf, uint16_t* __restrict__ Cb,
        int M, int N, int K, int epi) {
    extern __shared__ uint16_t smb[];

    const int tid = threadIdx.x;
    const int bm = blockIdx.y * 128, bn = blockIdx.x * 128;
    const int koff = blockIdx.z * K;
    const int warp = tid >> 5, lane = tid & 31;
    const int wm = (warp & 3) * 32;
    const int wn = (warp >> 2) * 64;
    const int g  = lane >> 2, t = lane & 3;

    const uint16_t* Ab0 = A  + (size_t)bm * lda + koff;
    const uint16_t* Bb0 = Bt + (size_t)bn * ldb + koff;

    auto loadStage = [&](int kt, int stage) {
        uint16_t* As = smb + stage * STAGE_ELEMS;
        uint16_t* Bs = As + ATILE;
        #pragma unroll
        for (int i = 0; i < 4; i++) {
            int idx = tid + i * 256;
            int r = idx >> 3, c = idx & 7;
            cp_async16(As + r * ASTR + c * 8, Ab0 + (size_t)r * lda + kt * BKT + c * 8);
            cp_async16(Bs + r * ASTR + c * 8, Bb0 + (size_t)r * ldb + kt * BKT + c * 8);
        }
    };

    float acc[2][8][4];
    #pragma unroll
    for (int i = 0; i < 2; i++)
        #pragma unroll
        for (int j = 0; j < 8; j++)
            #pragma unroll
            for (int q = 0; q < 4; q++) acc[i][j][q] = 0.f;

    // per-lane ldmatrix base offsets (bytes within a stage)
    const uint32_t smemBase = (uint32_t)__cvta_generic_to_shared(smb);
    const int arow = lane & 15, ahalf = lane >> 4;
    const uint32_t aoff0 = (uint32_t)(((wm      + arow) * ASTR + ahalf * 8) * 2);
    const uint32_t aoff1 = (uint32_t)(((wm + 16 + arow) * ASTR + ahalf * 8) * 2);
    uint32_t boff[4];
    #pragma unroll
    for (int p = 0; p < 4; p++)
        boff[p] = (uint32_t)(((wn + p * 16 + arow) * ASTR + ahalf * 8) * 2) + ATILE * 2;

    const int nk = K / BKT;
    loadStage(0, 0);
    asm volatile("cp.async.commit_group;\n" ::);
    if (nk > 1) loadStage(1, 1);
    asm volatile("cp.async.commit_group;\n" ::);

    for (int kt = 0; kt < nk; kt++) {
        if (kt + 2 < nk) loadStage(kt + 2, (kt + 2) % TGSTAGES);
        asm volatile("cp.async.commit_group;\n" ::);
        asm volatile("cp.async.wait_group 2;\n" ::);
        __syncthreads();

        const uint32_t st = smemBase + (kt % TGSTAGES) * STAGE_BYTES;

        #pragma unroll
        for (int ks = 0; ks < 4; ks++) {
            const uint32_t kadd = ks * 32;   // 16 bf16 = 32 bytes
            uint32_t af[2][4], bw[4][4];
            LDSM_X4(af[0][0], af[0][1], af[0][2], af[0][3], st + aoff0 + kadd);
            LDSM_X4(af[1][0], af[1][1], af[1][2], af[1][3], st + aoff1 + kadd);
            #pragma unroll
            for (int p = 0; p < 4; p++)
                LDSM_X4(bw[p][0], bw[p][1], bw[p][2], bw[p][3], st + boff[p] + kadd);
            #pragma unroll
            for (int mt = 0; mt < 2; mt++)
                #pragma unroll
                for (int nt = 0; nt < 8; nt++) {
                    uint32_t b0 = bw[nt >> 1][nt & 1];
                    uint32_t b1 = bw[nt >> 1][2 + (nt & 1)];
                    asm volatile(
                        "mma.sync.aligned.m16n8k16.row.col.f32.bf16.bf16.f32 "
                        "{%0,%1,%2,%3}, {%4,%5,%6,%7}, {%8,%9}, {%0,%1,%2,%3};\n"
                        : "+f"(acc[mt][nt][0]), "+f"(acc[mt][nt][1]),
                          "+f"(acc[mt][nt][2]), "+f"(acc[mt][nt][3])
                        : "r"(af[mt][0]), "r"(af[mt][1]), "r"(af[mt][2]), "r"(af[mt][3]),
                          "r"(b0), "r"(b1));
                }
        }
        __syncthreads();
    }

    float* Cout = (epi == 3) ? (Cf + (size_t)blockIdx.z * M * N) : Cf;
    #pragma unroll
    for (int mt = 0; mt < 2; mt++) {
        #pragma unroll
        for (int nt = 0; nt < 8; nt++) {
            int c = bn + wn + nt * 8 + t * 2;
            float bx = 0.f, by = 0.f;
            if (epi != 3) { bx = bias[c]; by = bias[c + 1]; }
            #pragma unroll
            for (int rr = 0; rr < 2; rr++) {
                int gm = bm + wm + mt * 16 + g + rr * 8;
                size_t off = (size_t)gm * N + c;
                float vx = acc[mt][nt][rr * 2 + 0] + bx;
                float vy = acc[mt][nt][rr * 2 + 1] + by;
                if (epi == 1) {
                    *(uint32_t*)&Cb[off] = pack_bf2(gelu_tanh(vx), gelu_tanh(vy));
                } else {
                    *(float2*)&Cout[off] = make_float2(vx, vy);
                }
            }
        }
    }
}

// ---------------- causal attention (fp32 in, bf16 out) ----------------
__global__ void __launch_bounds__(256) attn_kernel(
        const float* __restrict__ qkv, uint16_t* __restrict__ o) {
    const int qt = blockIdx.x, hh = blockIdx.y, b = blockIdx.z;
    const int tid = threadIdx.x;
    const int ql = tid >> 2, part = tid & 3;
    const int q  = qt * 64 + ql;

    __shared__ float Ks[64 * 68];
    __shared__ float Vs[64 * 68];

    float qreg[16], acc[16];
    const float* qp = qkv + (size_t)(b * TTOT + q) * (3 * DIM) + hh * HDIM + part * 16;
    #pragma unroll
    for (int i = 0; i < 4; i++) {
        float4 v = ((const float4*)qp)[i];
        qreg[4*i+0] = v.x; qreg[4*i+1] = v.y; qreg[4*i+2] = v.z; qreg[4*i+3] = v.w;
    }
    #pragma unroll
    for (int d = 0; d < 16; d++) acc[d] = 0.f;
    float mrun = -1e30f, lrun = 0.f;

    const int nkt = qt + 1;
    for (int kt = 0; kt < nkt; kt++) {
        {
            int r = tid >> 2, c = (tid & 3) * 16;
            const float* kp = qkv + (size_t)(b * TTOT + kt * 64 + r) * (3 * DIM)
                              + DIM + hh * HDIM + c;
            const float* vp = kp + DIM;
            #pragma unroll
            for (int i = 0; i < 4; i++) {
                float4 kv = ((const float4*)kp)[i];
                float4 vv = ((const float4*)vp)[i];
                int cb = c + i * 4;
                Ks[r * 68 + swz(cb+0)] = kv.x; Ks[r * 68 + swz(cb+1)] = kv.y;
                Ks[r * 68 + swz(cb+2)] = kv.z; Ks[r * 68 + swz(cb+3)] = kv.w;
                Vs[r * 68 + swz(cb+0)] = vv.x; Vs[r * 68 + swz(cb+1)] = vv.y;
                Vs[r * 68 + swz(cb+2)] = vv.z; Vs[r * 68 + swz(cb+3)] = vv.w;
            }
        }
        __syncthreads();

        const int pbase = part * 17;
        for (int j = 0; j < 64; j++) {
            const float* kr = &Ks[j * 68 + pbase];
            float s = 0.f;
            #pragma unroll
            for (int d = 0; d < 16; d++) s = fmaf(qreg[d], kr[d], s);
            s += __shfl_xor_sync(0xffffffffu, s, 1);
            s += __shfl_xor_sync(0xffffffffu, s, 2);
            s *= 0.125f;
            int kg = kt * 64 + j;
            s = (kg <= q) ? s : -1e30f;
            if (s > mrun) {
                float corr = __expf(mrun - s);
                lrun *= corr;
                #pragma unroll
                for (int d = 0; d < 16; d++) acc[d] *= corr;
                mrun = s;
            }
            float p = __expf(s - mrun);
            lrun += p;
            const float* vr = &Vs[j * 68 + pbase];
            #pragma unroll
            for (int d = 0; d < 16; d++) acc[d] = fmaf(p, vr[d], acc[d]);
        }
        __syncthreads();
    }

    float inv = 1.0f / lrun;
    uint16_t* op = o + (size_t)(b * TTOT + q) * DIM + hh * HDIM + part * 16;
    uint4 u0, u1;
    u0.x = pack_bf2(acc[0]*inv,  acc[1]*inv);  u0.y = pack_bf2(acc[2]*inv,  acc[3]*inv);
    u0.z = pack_bf2(acc[4]*inv,  acc[5]*inv);  u0.w = pack_bf2(acc[6]*inv,  acc[7]*inv);
    u1.x = pack_bf2(acc[8]*inv,  acc[9]*inv);  u1.y = pack_bf2(acc[10]*inv, acc[11]*inv);
    u1.z = pack_bf2(acc[12]*inv, acc[13]*inv); u1.w = pack_bf2(acc[14]*inv, acc[15]*inv);
    ((uint4*)op)[0] = u0;
    ((uint4*)op)[1] = u1;
}

// ---------------- finalize: fp32 LN of last tokens + eos + cur init ----------------
__global__ void __launch_bounds__(256) finalize_kernel(
        const float* __restrict__ h, const float* __restrict__ noise,
        const float* __restrict__ ong, const float* __restrict__ onb,
        const float* __restrict__ Weos, const float* __restrict__ beos,
        float* __restrict__ last, float* __restrict__ cur,
        float* __restrict__ out, int out_size) {
    int b = blockIdx.x, tid = threadIdx.x;
    float4 v = ((const float4*)(h + (size_t)(b * TTOT + TTOT - 1) * DIM))[tid];
    float s  = v.x + v.y + v.z + v.w;
    float ss = v.x*v.x + v.y*v.y + v.z*v.z + v.w*v.w;
    #pragma unroll
    for (int o = 16; o; o >>= 1) {
        s  += __shfl_xor_sync(0xffffffffu, s,  o);
        ss += __shfl_xor_sync(0xffffffffu, ss, o);
    }
    __shared__ float sh[16];
    int w = tid >> 5, l = tid & 31;
    if (l == 0) { sh[w] = s; sh[8 + w] = ss; }
    __syncthreads();
    float S = 0.f, SS = 0.f;
    #pragma unroll
    for (int i = 0; i < 8; i++) { S += sh[i]; SS += sh[8 + i]; }
    float mean = S * (1.0f / DIM);
    float var  = SS * (1.0f / DIM) - mean * mean;
    float rs   = rsqrtf(var + 1e-5f);
    float4 gg = ((const float4*)ong)[tid];
    float4 bb = ((const float4*)onb)[tid];
    float4 nv;
    nv.x = (v.x - mean) * rs * gg.x + bb.x;
    nv.y = (v.y - mean) * rs * gg.y + bb.y;
    nv.z = (v.z - mean) * rs * gg.z + bb.z;
    nv.w = (v.w - mean) * rs * gg.w + bb.w;
    ((float4*)(last + (size_t)b * DIM))[tid] = nv;
    float4 we = ((const float4*)Weos)[tid];
    float p = nv.x*we.x + nv.y*we.y + nv.z*we.z + nv.w*we.w;
    __shared__ float red[256];
    red[tid] = p;
    __syncthreads();
    for (int st = 128; st; st >>= 1) {
        if (tid < st) red[tid] += red[tid + st];
        __syncthreads();
    }
    if (tid == 0 && (1024 + b) < out_size) {
        float e = red[0] + beos[0];
        out[1024 + b] = (e > 0.5f) ? 1.0f : 0.0f;
    }
    if (tid < LDIMC) cur[b * LDIMC + tid] = noise[b * LDIMC + tid];
}

// ---------------- persistent flow decoder ----------------
#define FLOW_BLOCKS 128
#define FLOW_SMEM ((8*KP1 + 8*HID)*4)

__device__ __forceinline__ void gbar(unsigned expect) {
    __syncthreads();
    if (threadIdx.x == 0) {
        __threadfence();
        unsigned a = atomicAdd(&g_bar_cnt, 1u);
        if (a == FLOW_BLOCKS - 1) {
            atomicExch(&g_bar_cnt, 0u);
            __threadfence();
            atomicAdd(&g_bar_gen, 1u);
        } else {
            while (*((volatile unsigned*)&g_bar_gen) != expect) { }
            __threadfence();
        }
    }
    __syncthreads();
}

__global__ void __launch_bounds__(256) flow_all_kernel(
        const float* __restrict__ last, float* __restrict__ cur,
        const float* __restrict__ Wf1t, const float* __restrict__ bf1,
        const float* __restrict__ Wf2t, const float* __restrict__ bf2,
        const float* __restrict__ Wf3t, const float* __restrict__ bf3,
        float* __restrict__ f1, float* __restrict__ f2) {
    extern __shared__ float shf[];
    float* xs1 = shf;
    float* xs2 = shf + 8 * KP1;
    const int tid = threadIdx.x, blk = blockIdx.x;
    const int warp = tid >> 5, lane = tid & 31;

    unsigned gen0 = *((volatile unsigned*)&g_bar_gen);
    unsigned bc = 0;

    for (int i = tid; i < 8 * 1024; i += 256) {
        int m = i >> 10, k = i & 1023;
        xs1[m * KP1 + k] = last[m * 1024 + k];
    }
    if (tid < 48) {
        int m = tid / 6, k = KF1 + tid % 6;
        xs1[m * KP1 + k] = 0.f;
    }

    for (int step = 0; step < NSTEPS; step++) {
        float sv = (float)step / NSTEPS;
        float tv = (float)(step + 1) / NSTEPS;
        for (int i = tid; i < 8 * LDIMC; i += 256) {
            int m = i >> 7, k = i & 127;
            xs1[m * KP1 + 1026 + k] = cur[i];
        }
        if (tid < 16) {
            int m = tid >> 1;
            xs1[m * KP1 + 1024 + (tid & 1)] = (tid & 1) ? tv : sv;
        }
        __syncthreads();

        {
            int n = blk * 8 + warp;
            const float* wp = Wf1t + (size_t)n * KP1;
            float acc[8] = {0,0,0,0,0,0,0,0};
            for (int k0 = lane * 4; k0 < KP1; k0 += 128) {
                float4 w4 = *(const float4*)&wp[k0];
                #pragma unroll
                for (int m = 0; m < 8; m++) {
                    float4 x4 = *(const float4*)&xs1[m * KP1 + k0];
                    acc[m] += w4.x*x4.x + w4.y*x4.y + w4.z*x4.z + w4.w*x4.w;
                }
            }
            #pragma unroll
            for (int m = 0; m < 8; m++) {
                float v = acc[m];
                #pragma unroll
                for (int o2 = 16; o2; o2 >>= 1) v += __shfl_xor_sync(0xffffffffu, v, o2);
                acc[m] = v;
            }
            if (lane == 0) {
                float bn = bf1[n];
                #pragma unroll
                for (int m = 0; m < 8; m++) f1[m * HID + n] = silu(acc[m] + bn);
            }
        }
        gbar(gen0 + ++bc);

        for (int i = tid * 4; i < 8 * HID; i += 1024)
            *(float4*)&xs2[i] = *(const float4*)&f1[i];
        __syncthreads();
        {
            int n = blk * 8 + warp;
            const float* wp = Wf2t + (size_t)n * HID;
            float acc[8] = {0,0,0,0,0,0,0,0};
            for (int k0 = lane * 4; k0 < HID; k0 += 128) {
                float4 w4 = *(const float4*)&wp[k0];
                #pragma unroll
                for (int m = 0; m < 8; m++) {
                    float4 x4 = *(const float4*)&xs2[m * HID + k0];
                    acc[m] += w4.x*x4.x + w4.y*x4.y + w4.z*x4.z + w4.w*x4.w;
                }
            }
            #pragma unroll
            for (int m = 0; m < 8; m++) {
                float v = acc[m];
                #pragma unroll
                for (int o2 = 16; o2; o2 >>= 1) v += __shfl_xor_sync(0xffffffffu, v, o2);
                acc[m] = v;
            }
            if (lane == 0) {
                float bn = bf2[n];
                #pragma unroll
                for (int m = 0; m < 8; m++) f2[m * HID + n] = silu(acc[m] + bn);
            }
        }
        gbar(gen0 + ++bc);

        if (blk < 16) {
            for (int i = tid * 4; i < 8 * HID; i += 1024)
                *(float4*)&xs2[i] = *(const float4*)&f2[i];
            __syncthreads();
            int n = blk * 8 + warp;
            const float* wp = Wf3t + (size_t)n * HID;
            float acc[8] = {0,0,0,0,0,0,0,0};
            for (int k0 = lane * 4; k0 < HID; k0 += 128) {
                float4 w4 = *(const float4*)&wp[k0];
                #pragma unroll
                for (int m = 0; m < 8; m++) {
                    float4 x4 = *(const float4*)&xs2[m * HID + k0];
                    acc[m] += w4.x*x4.x + w4.y*x4.y + w4.z*x4.z + w4.w*x4.w;
                }
            }
            #pragma unroll
            for (int m = 0; m < 8; m++) {
                float v = acc[m];
                #pragma unroll
                for (int o2 = 16; o2; o2 >>= 1) v += __shfl_xor_sync(0xffffffffu, v, o2);
                acc[m] = v;
            }
            if (lane == 0) {
                float bn = bf3[n];
                #pragma unroll
                for (int m = 0; m < 8; m++)
                    cur[m * LDIMC + n] += (acc[m] + bn) * (1.0f / NSTEPS);
            }
        }
        gbar(gen0 + ++bc);
    }
}

__global__ void writeout_kernel(const float* __restrict__ cur,
                                float* __restrict__ out, int out_size) {
    int i = blockIdx.x * blockDim.x + threadIdx.x;
    if (i >= out_size) return;
    if (i < 1024)       out[i] = cur[i];
    else if (i >= 1032) out[i] = 0.0f;
}

// ---------------- host orchestration ----------------
extern "C" void kernel_launch(void* const* d_in, const int* in_sizes, int n_in,
                              void* d_out, int out_size) {
    const float* seq   = (const float*)d_in[0];
    const float* text  = (const float*)d_in[1];
    const float* noise = (const float*)d_in[2];
    const float* bos   = (const float*)d_in[4];
    const float* W_in  = (const float*)d_in[5];
    const float* b_in  = (const float*)d_in[6];
    const float* ln1g  = (const float*)d_in[7];
    const float* ln1b  = (const float*)d_in[8];
    const float* Wqkv  = (const float*)d_in[9];
    const float* bqkv  = (const float*)d_in[10];
    const float* Wo    = (const float*)d_in[11];
    const float* bo    = (const float*)d_in[12];
    const float* ln2g  = (const float*)d_in[13];
    const float* ln2b  = (const float*)d_in[14];
    const float* W1    = (const float*)d_in[15];
    const float* b1    = (const float*)d_in[16];
    const float* W2    = (const float*)d_in[17];
    const float* b2    = (const float*)d_in[18];
    const float* ong   = (const float*)d_in[19];
    const float* onb   = (const float*)d_in[20];
    const float* Weos  = (const float*)d_in[21];
    const float* beos  = (const float*)d_in[22];
    const float* Wf1   = (const float*)d_in[23];
    const float* bf1   = (const float*)d_in[24];
    const float* Wf2   = (const float*)d_in[25];
    const float* bf2   = (const float*)d_in[26];
    const float* Wf3   = (const float*)d_in[27];
    const float* bf3   = (const float*)d_in[28];
    float* out = (float*)d_out;

    uint16_t *p_seqb, *p_tmpb, *p_attb, *p_midb;
    uint16_t *p_wint, *p_wqkvt, *p_wot, *p_w1t, *p_w2t;
    float *p_x, *p_h, *p_qkv, *p_last, *p_cur, *p_f1, *p_f2, *p_p01;
    float *p_wf1t, *p_wf2t, *p_wf3t;
    cudaGetSymbolAddress((void**)&p_seqb,  g_seqb);
    cudaGetSymbolAddress((void**)&p_tmpb,  g_tmpb);
    cudaGetSymbolAddress((void**)&p_attb,  g_attb);
    cudaGetSymbolAddress((void**)&p_midb,  g_midb);
    cudaGetSymbolAddress((void**)&p_wint,  g_wint);
    cudaGetSymbolAddress((void**)&p_wqkvt, g_wqkvt);
    cudaGetSymbolAddress((void**)&p_wot,   g_wot);
    cudaGetSymbolAddress((void**)&p_w1t,   g_w1t);
    cudaGetSymbolAddress((void**)&p_w2t,   g_w2t);
    cudaGetSymbolAddress((void**)&p_x,     g_x);
    cudaGetSymbolAddress((void**)&p_h,     g_h);
    cudaGetSymbolAddress((void**)&p_qkv,   g_qkv);
    cudaGetSymbolAddress((void**)&p_last,  g_last);
    cudaGetSymbolAddress((void**)&p_cur,   g_cur);
    cudaGetSymbolAddress((void**)&p_f1,    g_f1);
    cudaGetSymbolAddress((void**)&p_f2,    g_f2);
    cudaGetSymbolAddress((void**)&p_p01,   g_p01);
    cudaGetSymbolAddress((void**)&p_wf1t,  g_wf1t);
    cudaGetSymbolAddress((void**)&p_wf2t,  g_wf2t);
    cudaGetSymbolAddress((void**)&p_wf3t,  g_wf3t);

    cudaFuncSetAttribute(tgemm_bf16,
                         cudaFuncAttributeMaxDynamicSharedMemorySize, TG_SMEM);
    cudaFuncSetAttribute(flow_all_kernel,
                         cudaFuncAttributeMaxDynamicSharedMemorySize, FLOW_SMEM);

    dim3 tb(32, 8);
    int nseq = BDIM * TSEQ * LDIMC;

    // (same launch order as R7 so ncu captures the same input-proj GEMM for A/B compare)
    tconv_kernel<<<dim3(DIM/32,  LDIMC/64, 1),      tb>>>(W_in, p_wint,  LDIMC, DIM);
    nanfix_kernel<<<(nseq + 255)/256, 256>>>(seq, bos, p_seqb, nseq);
    tconv_kernel<<<dim3(3*DIM/32, DIM/64, NLAYER),  tb>>>(Wqkv, p_wqkvt, DIM, 3*DIM);
    tgemm_bf16<<<dim3(DIM/128, (BDIM*TSEQ)/128, 1), 256, TG_SMEM>>>(
        p_seqb, LDIMC, p_wint, LDIMC, b_in, p_x, nullptr, BDIM*TSEQ, DIM, LDIMC, 0);
    concat_ln_kernel<<<MROWS, 256>>>(text, p_x, p_h, p_tmpb, ln1g, ln1b);
    tgemm_bf16<<<dim3(3*DIM/128, MROWS/128, 1), 256, TG_SMEM>>>(
        p_tmpb, DIM, p_wqkvt, DIM, bqkv, p_qkv, nullptr, MROWS, 3*DIM, DIM, 0);

    // remaining weight prep
    tconv_kernel<<<dim3(DIM/32,  DIM/64, NLAYER),   tb>>>(Wo,   p_wot,   DIM, DIM);
    tconv_kernel<<<dim3(FFN/32,  DIM/64, NLAYER),   tb>>>(W1,   p_w1t,   DIM, FFN);
    tconv_kernel<<<dim3(DIM/32,  FFN/64, NLAYER),   tb>>>(W2,   p_w2t,   FFN, DIM);
    zero_kernel<<<(HID*KP1 + 255)/256, 256>>>(p_wf1t, HID*KP1);
    transpose_kernel<<<dim3((HID+31)/32, (KF1+31)/32), tb>>>(Wf1, p_wf1t, KF1, HID, KP1);
    transpose_kernel<<<dim3((HID+31)/32, (HID+31)/32), tb>>>(Wf2, p_wf2t, HID, HID, HID);
    transpose_kernel<<<dim3((LDIMC+31)/32, (HID+31)/32), tb>>>(Wf3, p_wf3t, HID, LDIMC, HID);

    // transformer layers (QKV for layer l+1 launched at end of layer l)
    for (int l = 0; l < NLAYER; l++) {
        attn_kernel<<<dim3(TTOT/64, HEADS, BDIM), 256>>>(p_qkv, p_attb);
        tgemm_bf16<<<dim3(DIM/128, MROWS/128, 2), 256, TG_SMEM>>>(
            p_attb, DIM, p_wot + (size_t)l*DIM*DIM, DIM,
            nullptr, p_p01, nullptr, MROWS, DIM, 512, 3);
        combine_ln_kernel<<<MROWS, 256>>>(
            p_p01, p_p01 + (size_t)MROWS*DIM, bo + l*DIM, p_h,
            ln2g + l*DIM, ln2b + l*DIM, p_tmpb, 1);
        tgemm_bf16<<<dim3(FFN/128, MROWS/128, 1), 256, TG_SMEM>>>(
            p_tmpb, DIM, p_w1t + (size_t)l*FFN*DIM, DIM,
            b1 + l*FFN, nullptr, p_midb, MROWS, FFN, DIM, 1);
        tgemm_bf16<<<dim3(DIM/128, MROWS/128, 2), 256, TG_SMEM>>>(
            p_midb, FFN, p_w2t + (size_t)l*DIM*FFN, FFN,
            nullptr, p_p01, nullptr, MROWS, DIM, 2048, 3);
        if (l < NLAYER - 1) {
            combine_ln_kernel<<<MROWS, 256>>>(
                p_p01, p_p01 + (size_t)MROWS*DIM, b2 + l*DIM, p_h,
                ln1g + (l+1)*DIM, ln1b + (l+1)*DIM, p_tmpb, 1);
            tgemm_bf16<<<dim3(3*DIM/128, MROWS/128, 1), 256, TG_SMEM>>>(
                p_tmpb, DIM, p_wqkvt + (size_t)(l+1)*3*DIM*DIM, DIM,
                bqkv + (l+1)*3*DIM, p_qkv, nullptr, MROWS, 3*DIM, DIM, 0);
        } else {
            combine_ln_kernel<<<MROWS, 256>>>(
                p_p01, p_p01 + (size_t)MROWS*DIM, b2 + l*DIM, p_h,
                nullptr, nullptr, nullptr, 0);
        }
    }

    // finalize: fp32 LN on last tokens only + eos + cur init
    finalize_kernel<<<BDIM, 256>>>(p_h, noise, ong, onb, Weos, beos,
                                   p_last, p_cur, out, out_size);

    // persistent flow decoder
    flow_all_kernel<<<FLOW_BLOCKS, 256, FLOW_SMEM>>>(
        p_last, p_cur, p_wf1t, bf1, p_wf2t, bf2, p_wf3t, bf3, p_f1, p_f2);

    // write output
    int ncov = out_size > 1024 ? out_size : 1024;
    writeout_kernel<<<(ncov + 255)/256, 256>>>(p_cur, out, out_size);
}

// round 10
// speedup vs baseline: 1.0065x; 1.0065x over previous
#include <cuda_runtime.h>
#include <cuda_bf16.h>
#include <math.h>
#include <stdint.h>

// ---------------- model constants ----------------
#define BDIM   8
#define TTXT   64
#define TSEQ   256
#define TTOT   320
#define MROWS  (BDIM*TTOT)    // 2560
#define DIM    1024
#define LDIMC  128
#define FFN    4096
#define HEADS  16
#define HDIM   64
#define NLAYER 4
#define HID    1024
#define KF1    1154
#define KP1    1160
#define NSTEPS 16

// ---------------- scratch ----------------
__device__ __align__(16) uint16_t g_seqb[BDIM*TSEQ*LDIMC];
__device__ __align__(16) float    g_x   [BDIM*TSEQ*DIM];
__device__ __align__(16) float    g_h   [MROWS*DIM];
__device__ __align__(16) uint16_t g_tmpb[MROWS*DIM];
__device__ __align__(16) float    g_qkv [MROWS*3*DIM];
__device__ __align__(16) uint16_t g_attb[MROWS*DIM];
__device__ __align__(16) uint16_t g_midb[MROWS*FFN];
__device__ __align__(16) float    g_last[BDIM*DIM];
__device__ __align__(16) float    g_cur [BDIM*LDIMC];
__device__ __align__(16) float    g_f1  [BDIM*HID];
__device__ __align__(16) float    g_f2  [BDIM*HID];
__device__ __align__(16) float    g_p01 [2*MROWS*DIM];
// bf16 transposed weights  W^T [N][K]
__device__ __align__(16) uint16_t g_wint [DIM*LDIMC];
__device__ __align__(16) uint16_t g_wqkvt[NLAYER*3*DIM*DIM];
__device__ __align__(16) uint16_t g_wot  [NLAYER*DIM*DIM];
__device__ __align__(16) uint16_t g_w1t  [NLAYER*FFN*DIM];
__device__ __align__(16) uint16_t g_w2t  [NLAYER*DIM*FFN];
// fp32 transposed flow weights
__device__ __align__(16) float g_wf1t[HID*KP1];
__device__ __align__(16) float g_wf2t[HID*HID];
__device__ __align__(16) float g_wf3t[LDIMC*HID];
// grid barrier state
__device__ unsigned g_bar_cnt = 0;
__device__ unsigned g_bar_gen = 0;

// ---------------- helpers ----------------
__device__ __forceinline__ float gelu_tanh(float x) {
    const float c = 0.7978845608028654f;
    float t = c * (x + 0.044715f * x * x * x);
    return 0.5f * x * (1.0f + tanhf(t));
}
__device__ __forceinline__ float silu(float x) { return x / (1.0f + __expf(-x)); }
__device__ __forceinline__ uint32_t pack_bf2(float a, float b) {
    __nv_bfloat162 h2 = __floats2bfloat162_rn(a, b);
    return *(uint32_t*)&h2;
}
__device__ __forceinline__ uint16_t bf16u(float a) {
    __nv_bfloat16 h = __float2bfloat16_rn(a);
    return *(uint16_t*)&h;
}
__device__ __forceinline__ void cp_async16(void* smem_dst, const void* gmem_src) {
    uint32_t s = (uint32_t)__cvta_generic_to_shared(smem_dst);
    asm volatile("cp.async.cg.shared.global [%0], [%1], 16;\n" :: "r"(s), "l"(gmem_src));
}
__device__ __forceinline__ int swz(int c) { return c + (c >> 4); }
#define LDSM_X4(r0, r1, r2, r3, addr) \
    asm volatile("ldmatrix.sync.aligned.m8n8.x4.shared.b16 {%0,%1,%2,%3}, [%4];" \
                 : "=r"(r0), "=r"(r1), "=r"(r2), "=r"(r3) : "r"(addr))

// ---------------- prep kernels ----------------
__global__ void tconv_kernel(const float* __restrict__ src, uint16_t* __restrict__ dst,
                             int K, int N) {
    __shared__ float tile[32][65];
    const float* s = src + (size_t)blockIdx.z * K * N;
    uint16_t* d    = dst + (size_t)blockIdx.z * K * N;
    int k0 = blockIdx.y * 64, n0 = blockIdx.x * 32;
    int tx = threadIdx.x, ty = threadIdx.y;
    #pragma unroll
    for (int i = 0; i < 8; i++) {
        int kk = ty + i * 8;
        tile[tx][kk] = s[(size_t)(k0 + kk) * N + n0 + tx];
    }
    __syncthreads();
    #pragma unroll
    for (int i = 0; i < 4; i++) {
        int nn = ty + i * 8;
        uint32_t p = pack_bf2(tile[nn][2 * tx], tile[nn][2 * tx + 1]);
        *(uint32_t*)&d[(size_t)(n0 + nn) * K + k0 + 2 * tx] = p;
    }
}
__global__ void zero_kernel(float* __restrict__ p, int n) {
    int i = blockIdx.x * blockDim.x + threadIdx.x;
    if (i < n) p[i] = 0.f;
}
__global__ void transpose_kernel(const float* __restrict__ src, float* __restrict__ dst,
                                 int R, int C, int dstride) {
    __shared__ float tile[32][33];
    int c0 = blockIdx.x * 32, r0 = blockIdx.y * 32;
    int tx = threadIdx.x, ty = threadIdx.y;
    #pragma unroll
    for (int i = 0; i < 4; i++) {
        int rr = r0 + ty + i * 8, cc = c0 + tx;
        if (rr < R && cc < C) tile[ty + i * 8][tx] = src[(size_t)rr * C + cc];
    }
    __syncthreads();
    #pragma unroll
    for (int i = 0; i < 4; i++) {
        int cc = c0 + ty + i * 8, rr = r0 + tx;
        if (cc < C && rr < R) dst[(size_t)cc * dstride + rr] = tile[tx][ty + i * 8];
    }
}

__global__ void nanfix_kernel(const float* __restrict__ seq,
                              const float* __restrict__ bos,
                              uint16_t* __restrict__ out, int n) {
    int i = blockIdx.x * blockDim.x + threadIdx.x;
    if (i < n) {
        float v = seq[i];
        v = (v != v) ? bos[i & (LDIMC - 1)] : v;
        out[i] = bf16u(v);
    }
}

// ---------------- fused concat + LayerNorm ----------------
__global__ void __launch_bounds__(256) concat_ln_kernel(
        const float* __restrict__ text, const float* __restrict__ x,
        float* __restrict__ h, uint16_t* __restrict__ lnout,
        const float* __restrict__ g, const float* __restrict__ bta) {
    int row = blockIdx.x, tid = threadIdx.x;
    int b = row / TTOT, t = row - b * TTOT;
    float4 v;
    if (t < TTXT)
        v = ((const float4*)text)[(size_t)(b * TTXT + t) * 256 + tid];
    else
        v = ((const float4*)x)[(size_t)(b * TSEQ + (t - TTXT)) * 256 + tid];
    ((float4*)(h + (size_t)row * DIM))[tid] = v;

    float s  = v.x + v.y + v.z + v.w;
    float ss = v.x*v.x + v.y*v.y + v.z*v.z + v.w*v.w;
    #pragma unroll
    for (int o = 16; o; o >>= 1) {
        s  += __shfl_xor_sync(0xffffffffu, s,  o);
        ss += __shfl_xor_sync(0xffffffffu, ss, o);
    }
    __shared__ float sh[16];
    int w = tid >> 5, l = tid & 31;
    if (l == 0) { sh[w] = s; sh[8 + w] = ss; }
    __syncthreads();
    float S = 0.f, SS = 0.f;
    #pragma unroll
    for (int i = 0; i < 8; i++) { S += sh[i]; SS += sh[8 + i]; }
    float mean = S * (1.0f / DIM);
    float var  = SS * (1.0f / DIM) - mean * mean;
    float rs   = rsqrtf(var + 1e-5f);
    float4 gg = ((const float4*)g)[tid];
    float4 bb = ((const float4*)bta)[tid];
    uint2 o2;
    o2.x = pack_bf2((v.x - mean) * rs * gg.x + bb.x, (v.y - mean) * rs * gg.y + bb.y);
    o2.y = pack_bf2((v.z - mean) * rs * gg.z + bb.z, (v.w - mean) * rs * gg.w + bb.w);
    ((uint2*)(lnout + (size_t)row * DIM))[tid] = o2;
}

// ---------------- combine split-K partials + optional fused LN ----------------
__global__ void __launch_bounds__(256) combine_ln_kernel(
        const float* __restrict__ p0, const float* __restrict__ p1,
        const float* __restrict__ bias, float* __restrict__ h,
        const float* __restrict__ g, const float* __restrict__ bta,
        uint16_t* __restrict__ lnout, int do_ln) {
    int row = blockIdx.x, tid = threadIdx.x;
    size_t off = (size_t)row * DIM;
    float4 a  = ((const float4*)(p0 + off))[tid];
    float4 b4 = ((const float4*)(p1 + off))[tid];
    float4 r  = ((const float4*)(h + off))[tid];
    float4 bb = ((const float4*)bias)[tid];
    r.x += a.x + b4.x + bb.x;
    r.y += a.y + b4.y + bb.y;
    r.z += a.z + b4.z + bb.z;
    r.w += a.w + b4.w + bb.w;
    ((float4*)(h + off))[tid] = r;
    if (!do_ln) return;
    float s  = r.x + r.y + r.z + r.w;
    float ss = r.x*r.x + r.y*r.y + r.z*r.z + r.w*r.w;
    #pragma unroll
    for (int o = 16; o; o >>= 1) {
        s  += __shfl_xor_sync(0xffffffffu, s,  o);
        ss += __shfl_xor_sync(0xffffffffu, ss, o);
    }
    __shared__ float sh[16];
    int w = tid >> 5, l = tid & 31;
    if (l == 0) { sh[w] = s; sh[8 + w] = ss; }
    __syncthreads();
    float S = 0.f, SS = 0.f;
    #pragma unroll
    for (int i = 0; i < 8; i++) { S += sh[i]; SS += sh[8 + i]; }
    float mean = S * (1.0f / DIM);
    float var  = SS * (1.0f / DIM) - mean * mean;
    float rs   = rsqrtf(var + 1e-5f);
    float4 gg = ((const float4*)g)[tid];
    float4 b2 = ((const float4*)bta)[tid];
    uint2 o2;
    o2.x = pack_bf2((r.x - mean) * rs * gg.x + b2.x, (r.y - mean) * rs * gg.y + b2.y);
    o2.y = pack_bf2((r.z - mean) * rs * gg.z + b2.z, (r.w - mean) * rs * gg.w + b2.w);
    ((uint2*)(lnout + off))[tid] = o2;
}

// ---------------- bf16 tensor-core GEMM (mma.sync + ldmatrix, 2-stage cp.async) ----------------
#define BKT 64
#define ASTR 72
#define ATILE (128*ASTR)
#define STAGE_ELEMS (2*ATILE)
#define STAGE_BYTES (STAGE_ELEMS*2)
#define TG_SMEM (2*STAGE_BYTES)       // 73728 bytes

__global__ void __launch_bounds__(256, 2) tgemm_bf16(
        const uint16_t* __restrict__ A, int lda,
        const uint16_t* __restrict__ Bt, int ldb,
        const float* __restrict__ bias,
        float* __restrict__ Cf, uint16_t* __restrict__ Cb,
        int M, int N, int K, int epi) {
    extern __shared__ uint16_t smb[];

    const int tid = threadIdx.x;
    const int bm = blockIdx.y * 128, bn = blockIdx.x * 128;
    const int koff = blockIdx.z * K;
    const int warp = tid >> 5, lane = tid & 31;
    const int wm = (warp & 3) * 32;
    const int wn = (warp >> 2) * 64;
    const int g  = lane >> 2, t = lane & 3;

    const uint16_t* Ab0 = A  + (size_t)bm * lda + koff;
    const uint16_t* Bb0 = Bt + (size_t)bn * ldb + koff;

    auto loadStage = [&](int kt, int stage) {
        uint16_t* As = smb + stage * STAGE_ELEMS;
        uint16_t* Bs = As + ATILE;
        #pragma unroll
        for (int i = 0; i < 4; i++) {
            int idx = tid + i * 256;
            int r = idx >> 3, c = idx & 7;
            cp_async16(As + r * ASTR + c * 8, Ab0 + (size_t)r * lda + kt * BKT + c * 8);
            cp_async16(Bs + r * ASTR + c * 8, Bb0 + (size_t)r * ldb + kt * BKT + c * 8);
        }
        asm volatile("cp.async.commit_group;\n" ::);
    };

    float acc[2][8][4];
    #pragma unroll
    for (int i = 0; i < 2; i++)
        #pragma unroll
        for (int j = 0; j < 8; j++)
            #pragma unroll
            for (int q = 0; q < 4; q++) acc[i][j][q] = 0.f;

    const uint32_t smemBase = (uint32_t)__cvta_generic_to_shared(smb);
    const int arow = lane & 15, ahalf = lane >> 4;
    const uint32_t aoff0 = (uint32_t)(((wm      + arow) * ASTR + ahalf * 8) * 2);
    const uint32_t aoff1 = (uint32_t)(((wm + 16 + arow) * ASTR + ahalf * 8) * 2);
    uint32_t boff[4];
    #pragma unroll
    for (int p = 0; p < 4; p++)
        boff[p] = (uint32_t)(((wn + p * 16 + arow) * ASTR + ahalf * 8) * 2) + ATILE * 2;

    const int nk = K / BKT;
    loadStage(0, 0);

    for (int kt = 0; kt < nk; kt++) {
        if (kt + 1 < nk) {
            loadStage(kt + 1, (kt + 1) & 1);
            asm volatile("cp.async.wait_group 1;\n" ::);
        } else {
            asm volatile("cp.async.wait_group 0;\n" ::);
        }
        __syncthreads();

        const uint32_t st = smemBase + (kt & 1) * STAGE_BYTES;

        #pragma unroll
        for (int ks = 0; ks < 4; ks++) {
            const uint32_t kadd = ks * 32;
            uint32_t af[2][4], bw[4][4];
            LDSM_X4(af[0][0], af[0][1], af[0][2], af[0][3], st + aoff0 + kadd);
            LDSM_X4(af[1][0], af[1][1], af[1][2], af[1][3], st + aoff1 + kadd);
            #pragma unroll
            for (int p = 0; p < 4; p++)
                LDSM_X4(bw[p][0], bw[p][1], bw[p][2], bw[p][3], st + boff[p] + kadd);
            #pragma unroll
            for (int mt = 0; mt < 2; mt++)
                #pragma unroll
                for (int nt = 0; nt < 8; nt++) {
                    uint32_t b0 = bw[nt >> 1][nt & 1];
                    uint32_t b1 = bw[nt >> 1][2 + (nt & 1)];
                    asm volatile(
                        "mma.sync.aligned.m16n8k16.row.col.f32.bf16.bf16.f32 "
                        "{%0,%1,%2,%3}, {%4,%5,%6,%7}, {%8,%9}, {%0,%1,%2,%3};\n"
                        : "+f"(acc[mt][nt][0]), "+f"(acc[mt][nt][1]),
                          "+f"(acc[mt][nt][2]), "+f"(acc[mt][nt][3])
                        : "r"(af[mt][0]), "r"(af[mt][1]), "r"(af[mt][2]), "r"(af[mt][3]),
                          "r"(b0), "r"(b1));
                }
        }
        __syncthreads();
    }

    float* Cout = (epi == 3) ? (Cf + (size_t)blockIdx.z * M * N) : Cf;
    #pragma unroll
    for (int mt = 0; mt < 2; mt++) {
        #pragma unroll
        for (int nt = 0; nt < 8; nt++) {
            int c = bn + wn + nt * 8 + t * 2;
            float bx = 0.f, by = 0.f;
            if (epi != 3) { bx = bias[c]; by = bias[c + 1]; }
            #pragma unroll
            for (int rr = 0; rr < 2; rr++) {
                int gm = bm + wm + mt * 16 + g + rr * 8;
                size_t off = (size_t)gm * N + c;
                float vx = acc[mt][nt][rr * 2 + 0] + bx;
                float vy = acc[mt][nt][rr * 2 + 1] + by;
                if (epi == 1) {
                    *(uint32_t*)&Cb[off] = pack_bf2(gelu_tanh(vx), gelu_tanh(vy));
                } else {
                    *(float2*)&Cout[off] = make_float2(vx, vy);
                }
            }
        }
    }
}

// ---------------- causal attention (fp32 in, bf16 out) ----------------
// 4 threads per query; keys processed in chunks of 4 with per-thread exp + quad shfl share.
__global__ void __launch_bounds__(256) attn_kernel(
        const float* __restrict__ qkv, uint16_t* __restrict__ o) {
    const int qt = blockIdx.x, hh = blockIdx.y, b = blockIdx.z;
    const int tid = threadIdx.x;
    const int ql = tid >> 2, part = tid & 3;
    const int q  = qt * 64 + ql;

    __shared__ float Ks[64 * 68];
    __shared__ float Vs[64 * 68];

    float qreg[16], acc[16];
    const float* qp = qkv + (size_t)(b * TTOT + q) * (3 * DIM) + hh * HDIM + part * 16;
    #pragma unroll
    for (int i = 0; i < 4; i++) {
        float4 v = ((const float4*)qp)[i];
        qreg[4*i+0] = v.x; qreg[4*i+1] = v.y; qreg[4*i+2] = v.z; qreg[4*i+3] = v.w;
    }
    #pragma unroll
    for (int d = 0; d < 16; d++) acc[d] = 0.f;
    float mrun = -1e30f, lrun = 0.f;

    const int nkt = qt + 1;
    for (int kt = 0; kt < nkt; kt++) {
        {
            int r = tid >> 2, c = (tid & 3) * 16;
            const float* kp = qkv + (size_t)(b * TTOT + kt * 64 + r) * (3 * DIM)
                              + DIM + hh * HDIM + c;
            const float* vp = kp + DIM;
            #pragma unroll
            for (int i = 0; i < 4; i++) {
                float4 kv = ((const float4*)kp)[i];
                float4 vv = ((const float4*)vp)[i];
                int cb = c + i * 4;
                Ks[r * 68 + swz(cb+0)] = kv.x; Ks[r * 68 + swz(cb+1)] = kv.y;
                Ks[r * 68 + swz(cb+2)] = kv.z; Ks[r * 68 + swz(cb+3)] = kv.w;
                Vs[r * 68 + swz(cb+0)] = vv.x; Vs[r * 68 + swz(cb+1)] = vv.y;
                Vs[r * 68 + swz(cb+2)] = vv.z; Vs[r * 68 + swz(cb+3)] = vv.w;
            }
        }
        __syncthreads();

        const int pbase = part * 17;
        for (int j0 = 0; j0 < 64; j0 += 4) {
            float sj[4];
            #pragma unroll
            for (int jj = 0; jj < 4; jj++) {
                const float* kr = &Ks[(j0 + jj) * 68 + pbase];
                float s = 0.f;
                #pragma unroll
                for (int d = 0; d < 16; d++) s = fmaf(qreg[d], kr[d], s);
                s += __shfl_xor_sync(0xffffffffu, s, 1);
                s += __shfl_xor_sync(0xffffffffu, s, 2);
                s *= 0.125f;
                int kg = kt * 64 + j0 + jj;
                sj[jj] = (kg <= q) ? s : -1e30f;
            }
            float tmax = fmaxf(fmaxf(sj[0], sj[1]), fmaxf(sj[2], sj[3]));
            if (tmax > mrun) {
                float corr = __expf(mrun - tmax);
                lrun *= corr;
                #pragma unroll
                for (int d = 0; d < 16; d++) acc[d] *= corr;
                mrun = tmax;
            }
            float pm = __expf(sj[part] - mrun);
            float p0 = __shfl_sync(0xffffffffu, pm, 0, 4);
            float p1 = __shfl_sync(0xffffffffu, pm, 1, 4);
            float p2 = __shfl_sync(0xffffffffu, pm, 2, 4);
            float p3 = __shfl_sync(0xffffffffu, pm, 3, 4);
            lrun += p0 + p1 + p2 + p3;
            const float* vr0 = &Vs[(j0 + 0) * 68 + pbase];
            const float* vr1 = &Vs[(j0 + 1) * 68 + pbase];
            const float* vr2 = &Vs[(j0 + 2) * 68 + pbase];
            const float* vr3 = &Vs[(j0 + 3) * 68 + pbase];
            #pragma unroll
            for (int d = 0; d < 16; d++) {
                float a = acc[d];
                a = fmaf(p0, vr0[d], a);
                a = fmaf(p1, vr1[d], a);
                a = fmaf(p2, vr2[d], a);
                a = fmaf(p3, vr3[d], a);
                acc[d] = a;
            }
        }
        __syncthreads();
    }

    float inv = 1.0f / lrun;
    uint16_t* op = o + (size_t)(b * TTOT + q) * DIM + hh * HDIM + part * 16;
    uint4 u0, u1;
    u0.x = pack_bf2(acc[0]*inv,  acc[1]*inv);  u0.y = pack_bf2(acc[2]*inv,  acc[3]*inv);
    u0.z = pack_bf2(acc[4]*inv,  acc[5]*inv);  u0.w = pack_bf2(acc[6]*inv,  acc[7]*inv);
    u1.x = pack_bf2(acc[8]*inv,  acc[9]*inv);  u1.y = pack_bf2(acc[10]*inv, acc[11]*inv);
    u1.z = pack_bf2(acc[12]*inv, acc[13]*inv); u1.w = pack_bf2(acc[14]*inv, acc[15]*inv);
    ((uint4*)op)[0] = u0;
    ((uint4*)op)[1] = u1;
}

// ---------------- finalize ----------------
__global__ void __launch_bounds__(256) finalize_kernel(
        const float* __restrict__ h, const float* __restrict__ noise,
        const float* __restrict__ ong, const float* __restrict__ onb,
        const float* __restrict__ Weos, const float* __restrict__ beos,
        float* __restrict__ last, float* __restrict__ cur,
        float* __restrict__ out, int out_size) {
    int b = blockIdx.x, tid = threadIdx.x;
    float4 v = ((const float4*)(h + (size_t)(b * TTOT + TTOT - 1) * DIM))[tid];
    float s  = v.x + v.y + v.z + v.w;
    float ss = v.x*v.x + v.y*v.y + v.z*v.z + v.w*v.w;
    #pragma unroll
    for (int o = 16; o; o >>= 1) {
        s  += __shfl_xor_sync(0xffffffffu, s,  o);
        ss += __shfl_xor_sync(0xffffffffu, ss, o);
    }
    __shared__ float sh[16];
    int w = tid >> 5, l = tid & 31;
    if (l == 0) { sh[w] = s; sh[8 + w] = ss; }
    __syncthreads();
    float S = 0.f, SS = 0.f;
    #pragma unroll
    for (int i = 0; i < 8; i++) { S += sh[i]; SS += sh[8 + i]; }
    float mean = S * (1.0f / DIM);
    float var  = SS * (1.0f / DIM) - mean * mean;
    float rs   = rsqrtf(var + 1e-5f);
    float4 gg = ((const float4*)ong)[tid];
    float4 bb = ((const float4*)onb)[tid];
    float4 nv;
    nv.x = (v.x - mean) * rs * gg.x + bb.x;
    nv.y = (v.y - mean) * rs * gg.y + bb.y;
    nv.z = (v.z - mean) * rs * gg.z + bb.z;
    nv.w = (v.w - mean) * rs * gg.w + bb.w;
    ((float4*)(last + (size_t)b * DIM))[tid] = nv;
    float4 we = ((const float4*)Weos)[tid];
    float p = nv.x*we.x + nv.y*we.y + nv.z*we.z + nv.w*we.w;
    __shared__ float red[256];
    red[tid] = p;
    __syncthreads();
    for (int st = 128; st; st >>= 1) {
        if (tid < st) red[tid] += red[tid + st];
        __syncthreads();
    }
    if (tid == 0 && (1024 + b) < out_size) {
        float e = red[0] + beos[0];
        out[1024 + b] = (e > 0.5f) ? 1.0f : 0.0f;
    }
    if (tid < LDIMC) cur[b * LDIMC + tid] = noise[b * LDIMC + tid];
}

// ---------------- persistent flow decoder ----------------
#define FLOW_BLOCKS 128
#define FLOW_SMEM ((8*KP1 + 8*HID)*4)

__device__ __forceinline__ void gbar(unsigned expect) {
    __syncthreads();
    if (threadIdx.x == 0) {
        __threadfence();
        unsigned a = atomicAdd(&g_bar_cnt, 1u);
        if (a == FLOW_BLOCKS - 1) {
            atomicExch(&g_bar_cnt, 0u);
            __threadfence();
            atomicAdd(&g_bar_gen, 1u);
        } else {
            while (*((volatile unsigned*)&g_bar_gen) != expect) { }
            __threadfence();
        }
    }
    __syncthreads();
}

__global__ void __launch_bounds__(256) flow_all_kernel(
        const float* __restrict__ last, float* __restrict__ cur,
        const float* __restrict__ Wf1t, const float* __restrict__ bf1,
        const float* __restrict__ Wf2t, const float* __restrict__ bf2,
        const float* __restrict__ Wf3t, const float* __restrict__ bf3,
        float* __restrict__ f1, float* __restrict__ f2) {
    extern __shared__ float shf[];
    float* xs1 = shf;
    float* xs2 = shf + 8 * KP1;
    const int tid = threadIdx.x, blk = blockIdx.x;
    const int warp = tid >> 5, lane = tid & 31;

    unsigned gen0 = *((volatile unsigned*)&g_bar_gen);
    unsigned bc = 0;

    for (int i = tid; i < 8 * 1024; i += 256) {
        int m = i >> 10, k = i & 1023;
        xs1[m * KP1 + k] = last[m * 1024 + k];
    }
    if (tid < 48) {
        int m = tid / 6, k = KF1 + tid % 6;
        xs1[m * KP1 + k] = 0.f;
    }

    for (int step = 0; step < NSTEPS; step++) {
        float sv = (float)step / NSTEPS;
        float tv = (float)(step + 1) / NSTEPS;
        for (int i = tid; i < 8 * LDIMC; i += 256) {
            int m = i >> 7, k = i & 127;
            xs1[m * KP1 + 1026 + k] = cur[i];
        }
        if (tid < 16) {
            int m = tid >> 1;
            xs1[m * KP1 + 1024 + (tid & 1)] = (tid & 1) ? tv : sv;
        }
        __syncthreads();

        {
            int n = blk * 8 + warp;
            const float* wp = Wf1t + (size_t)n * KP1;
            float acc[8] = {0,0,0,0,0,0,0,0};
            for (int k0 = lane * 4; k0 < KP1; k0 += 128) {
                float4 w4 = *(const float4*)&wp[k0];
                #pragma unroll
                for (int m = 0; m < 8; m++) {
                    float4 x4 = *(const float4*)&xs1[m * KP1 + k0];
                    acc[m] += w4.x*x4.x + w4.y*x4.y + w4.z*x4.z + w4.w*x4.w;
                }
            }
            #pragma unroll
            for (int m = 0; m < 8; m++) {
                float v = acc[m];
                #pragma unroll
                for (int o2 = 16; o2; o2 >>= 1) v += __shfl_xor_sync(0xffffffffu, v, o2);
                acc[m] = v;
            }
            if (lane == 0) {
                float bn = bf1[n];
                #pragma unroll
                for (int m = 0; m < 8; m++) f1[m * HID + n] = silu(acc[m] + bn);
            }
        }
        gbar(gen0 + ++bc);

        for (int i = tid * 4; i < 8 * HID; i += 1024)
            *(float4*)&xs2[i] = *(const float4*)&f1[i];
        __syncthreads();
        {
            int n = blk * 8 + warp;
            const float* wp = Wf2t + (size_t)n * HID;
            float acc[8] = {0,0,0,0,0,0,0,0};
            for (int k0 = lane * 4; k0 < HID; k0 += 128) {
                float4 w4 = *(const float4*)&wp[k0];
                #pragma unroll
                for (int m = 0; m < 8; m++) {
                    float4 x4 = *(const float4*)&xs2[m * HID + k0];
                    acc[m] += w4.x*x4.x + w4.y*x4.y + w4.z*x4.z + w4.w*x4.w;
                }
            }
            #pragma unroll
            for (int m = 0; m < 8; m++) {
                float v = acc[m];
                #pragma unroll
                for (int o2 = 16; o2; o2 >>= 1) v += __shfl_xor_sync(0xffffffffu, v, o2);
                acc[m] = v;
            }
            if (lane == 0) {
                float bn = bf2[n];
                #pragma unroll
                for (int m = 0; m < 8; m++) f2[m * HID + n] = silu(acc[m] + bn);
            }
        }
        gbar(gen0 + ++bc);

        if (blk < 16) {
            for (int i = tid * 4; i < 8 * HID; i += 1024)
                *(float4*)&xs2[i] = *(const float4*)&f2[i];
            __syncthreads();
            int n = blk * 8 + warp;
            const float* wp = Wf3t + (size_t)n * HID;
            float acc[8] = {0,0,0,0,0,0,0,0};
            for (int k0 = lane * 4; k0 < HID; k0 += 128) {
                float4 w4 = *(const float4*)&wp[k0];
                #pragma unroll
                for (int m = 0; m < 8; m++) {
                    float4 x4 = *(const float4*)&xs2[m * HID + k0];
                    acc[m] += w4.x*x4.x + w4.y*x4.y + w4.z*x4.z + w4.w*x4.w;
                }
            }
            #pragma unroll
            for (int m = 0; m < 8; m++) {
                float v = acc[m];
                #pragma unroll
                for (int o2 = 16; o2; o2 >>= 1) v += __shfl_xor_sync(0xffffffffu, v, o2);
                acc[m] = v;
            }
            if (lane == 0) {
                float bn = bf3[n];
                #pragma unroll
                for (int m = 0; m < 8; m++)
                    cur[m * LDIMC + n] += (acc[m] + bn) * (1.0f / NSTEPS);
            }
        }
        gbar(gen0 + ++bc);
    }
}

__global__ void writeout_kernel(const float* __restrict__ cur,
                                float* __restrict__ out, int out_size) {
    int i = blockIdx.x * blockDim.x + threadIdx.x;
    if (i >= out_size) return;
    if (i < 1024)       out[i] = cur[i];
    else if (i >= 1032) out[i] = 0.0f;
}

// ---------------- host orchestration ----------------
extern "C" void kernel_launch(void* const* d_in, const int* in_sizes, int n_in,
                              void* d_out, int out_size) {
    const float* seq   = (const float*)d_in[0];
    const float* text  = (const float*)d_in[1];
    const float* noise = (const float*)d_in[2];
    const float* bos   = (const float*)d_in[4];
    const float* W_in  = (const float*)d_in[5];
    const float* b_in  = (const float*)d_in[6];
    const float* ln1g  = (const float*)d_in[7];
    const float* ln1b  = (const float*)d_in[8];
    const float* Wqkv  = (const float*)d_in[9];
    const float* bqkv  = (const float*)d_in[10];
    const float* Wo    = (const float*)d_in[11];
    const float* bo    = (const float*)d_in[12];
    const float* ln2g  = (const float*)d_in[13];
    const float* ln2b  = (const float*)d_in[14];
    const float* W1    = (const float*)d_in[15];
    const float* b1    = (const float*)d_in[16];
    const float* W2    = (const float*)d_in[17];
    const float* b2    = (const float*)d_in[18];
    const float* ong   = (const float*)d_in[19];
    const float* onb   = (const float*)d_in[20];
    const float* Weos  = (const float*)d_in[21];
    const float* beos  = (const float*)d_in[22];
    const float* Wf1   = (const float*)d_in[23];
    const float* bf1   = (const float*)d_in[24];
    const float* Wf2   = (const float*)d_in[25];
    const float* bf2   = (const float*)d_in[26];
    const float* Wf3   = (const float*)d_in[27];
    const float* bf3   = (const float*)d_in[28];
    float* out = (float*)d_out;

    uint16_t *p_seqb, *p_tmpb, *p_attb, *p_midb;
    uint16_t *p_wint, *p_wqkvt, *p_wot, *p_w1t, *p_w2t;
    float *p_x, *p_h, *p_qkv, *p_last, *p_cur, *p_f1, *p_f2, *p_p01;
    float *p_wf1t, *p_wf2t, *p_wf3t;
    cudaGetSymbolAddress((void**)&p_seqb,  g_seqb);
    cudaGetSymbolAddress((void**)&p_tmpb,  g_tmpb);
    cudaGetSymbolAddress((void**)&p_attb,  g_attb);
    cudaGetSymbolAddress((void**)&p_midb,  g_midb);
    cudaGetSymbolAddress((void**)&p_wint,  g_wint);
    cudaGetSymbolAddress((void**)&p_wqkvt, g_wqkvt);
    cudaGetSymbolAddress((void**)&p_wot,   g_wot);
    cudaGetSymbolAddress((void**)&p_w1t,   g_w1t);
    cudaGetSymbolAddress((void**)&p_w2t,   g_w2t);
    cudaGetSymbolAddress((void**)&p_x,     g_x);
    cudaGetSymbolAddress((void**)&p_h,     g_h);
    cudaGetSymbolAddress((void**)&p_qkv,   g_qkv);
    cudaGetSymbolAddress((void**)&p_last,  g_last);
    cudaGetSymbolAddress((void**)&p_cur,   g_cur);
    cudaGetSymbolAddress((void**)&p_f1,    g_f1);
    cudaGetSymbolAddress((void**)&p_f2,    g_f2);
    cudaGetSymbolAddress((void**)&p_p01,   g_p01);
    cudaGetSymbolAddress((void**)&p_wf1t,  g_wf1t);
    cudaGetSymbolAddress((void**)&p_wf2t,  g_wf2t);
    cudaGetSymbolAddress((void**)&p_wf3t,  g_wf3t);

    cudaFuncSetAttribute(tgemm_bf16,
                         cudaFuncAttributeMaxDynamicSharedMemorySize, TG_SMEM);
    cudaFuncSetAttribute(flow_all_kernel,
                         cudaFuncAttributeMaxDynamicSharedMemorySize, FLOW_SMEM);

    dim3 tb(32, 8);
    int nseq = BDIM * TSEQ * LDIMC;

    tconv_kernel<<<dim3(DIM/32,  LDIMC/64, 1),      tb>>>(W_in, p_wint,  LDIMC, DIM);
    nanfix_kernel<<<(nseq + 255)/256, 256>>>(seq, bos, p_seqb, nseq);
    tconv_kernel<<<dim3(3*DIM/32, DIM/64, NLAYER),  tb>>>(Wqkv, p_wqkvt, DIM, 3*DIM);
    tgemm_bf16<<<dim3(DIM/128, (BDIM*TSEQ)/128, 1), 256, TG_SMEM>>>(
        p_seqb, LDIMC, p_wint, LDIMC, b_in, p_x, nullptr, BDIM*TSEQ, DIM, LDIMC, 0);
    concat_ln_kernel<<<MROWS, 256>>>(text, p_x, p_h, p_tmpb, ln1g, ln1b);
    tgemm_bf16<<<dim3(3*DIM/128, MROWS/128, 1), 256, TG_SMEM>>>(
        p_tmpb, DIM, p_wqkvt, DIM, bqkv, p_qkv, nullptr, MROWS, 3*DIM, DIM, 0);

    // remaining weight prep
    tconv_kernel<<<dim3(DIM/32,  DIM/64, NLAYER),   tb>>>(Wo,   p_wot,   DIM, DIM);
    tconv_kernel<<<dim3(FFN/32,  DIM/64, NLAYER),   tb>>>(W1,   p_w1t,   DIM, FFN);
    tconv_kernel<<<dim3(DIM/32,  FFN/64, NLAYER),   tb>>>(W2,   p_w2t,   FFN, DIM);
    zero_kernel<<<(HID*KP1 + 255)/256, 256>>>(p_wf1t, HID*KP1);
    transpose_kernel<<<dim3((HID+31)/32, (KF1+31)/32), tb>>>(Wf1, p_wf1t, KF1, HID, KP1);
    transpose_kernel<<<dim3((HID+31)/32, (HID+31)/32), tb>>>(Wf2, p_wf2t, HID, HID, HID);
    transpose_kernel<<<dim3((LDIMC+31)/32, (HID+31)/32), tb>>>(Wf3, p_wf3t, HID, LDIMC, HID);

    // transformer layers (QKV for layer l+1 launched at end of layer l)
    for (int l = 0; l < NLAYER; l++) {
        attn_kernel<<<dim3(TTOT/64, HEADS, BDIM), 256>>>(p_qkv, p_attb);
        tgemm_bf16<<<dim3(DIM/128, MROWS/128, 2), 256, TG_SMEM>>>(
            p_attb, DIM, p_wot + (size_t)l*DIM*DIM, DIM,
            nullptr, p_p01, nullptr, MROWS, DIM, 512, 3);
        combine_ln_kernel<<<MROWS, 256>>>(
            p_p01, p_p01 + (size_t)MROWS*DIM, bo + l*DIM, p_h,
            ln2g + l*DIM, ln2b + l*DIM, p_tmpb, 1);
        tgemm_bf16<<<dim3(FFN/128, MROWS/128, 1), 256, TG_SMEM>>>(
            p_tmpb, DIM, p_w1t + (size_t)l*FFN*DIM, DIM,
            b1 + l*FFN, nullptr, p_midb, MROWS, FFN, DIM, 1);
        tgemm_bf16<<<dim3(DIM/128, MROWS/128, 2), 256, TG_SMEM>>>(
            p_midb, FFN, p_w2t + (size_t)l*DIM*FFN, FFN,
            nullptr, p_p01, nullptr, MROWS, DIM, 2048, 3);
        if (l < NLAYER - 1) {
            combine_ln_kernel<<<MROWS, 256>>>(
                p_p01, p_p01 + (size_t)MROWS*DIM, b2 + l*DIM, p_h,
                ln1g + (l+1)*DIM, ln1b + (l+1)*DIM, p_tmpb, 1);
            tgemm_bf16<<<dim3(3*DIM/128, MROWS/128, 1), 256, TG_SMEM>>>(
                p_tmpb, DIM, p_wqkvt + (size_t)(l+1)*3*DIM*DIM, DIM,
                bqkv + (l+1)*3*DIM, p_qkv, nullptr, MROWS, 3*DIM, DIM, 0);
        } else {
            combine_ln_kernel<<<MROWS, 256>>>(
                p_p01, p_p01 + (size_t)MROWS*DIM, b2 + l*DIM, p_h,
                nullptr, nullptr, nullptr, 0);
        }
    }

    // finalize
    finalize_kernel<<<BDIM, 256>>>(p_h, noise, ong, onb, Weos, beos,
                                   p_last, p_cur, out, out_size);

    // persistent flow decoder
    flow_all_kernel<<<FLOW_BLOCKS, 256, FLOW_SMEM>>>(
        p_last, p_cur, p_wf1t, bf1, p_wf2t, bf2, p_wf3t, bf3, p_f1, p_f2);

    // write output
    int ncov = out_size > 1024 ? out_size : 1024;
    writeout_kernel<<<(ncov + 255)/256, 256>>>(p_cur, out, out_size);
}

// round 11
// speedup vs baseline: 1.0401x; 1.0334x over previous
#include <cuda_runtime.h>
#include <cuda_bf16.h>
#include <math.h>
#include <stdint.h>

// ---------------- model constants ----------------
#define BDIM   8
#define TTXT   64
#define TSEQ   256
#define TTOT   320
#define MROWS  (BDIM*TTOT)    // 2560
#define DIM    1024
#define LDIMC  128
#define FFN    4096
#define HEADS  16
#define HDIM   64
#define NLAYER 4
#define HID    1024
#define KF1    1154
#define KP1    1160
#define NSTEPS 16
#define KSLICES 4

// ---------------- scratch ----------------
__device__ __align__(16) uint16_t g_seqb[BDIM*TSEQ*LDIMC];
__device__ __align__(16) float    g_x   [BDIM*TSEQ*DIM];
__device__ __align__(16) float    g_h   [MROWS*DIM];
__device__ __align__(16) uint16_t g_tmpb[MROWS*DIM];
__device__ __align__(16) float    g_qkv [MROWS*3*DIM];
__device__ __align__(16) uint16_t g_attb[MROWS*DIM];
__device__ __align__(16) uint16_t g_midb[MROWS*FFN];
__device__ __align__(16) float    g_last[BDIM*DIM];
__device__ __align__(16) float    g_cur [BDIM*LDIMC];
__device__ __align__(16) float    g_f1  [BDIM*HID];
__device__ __align__(16) float    g_f2  [BDIM*HID];
__device__ __align__(16) float    g_p01 [KSLICES*MROWS*DIM];
// bf16 transposed weights  W^T [N][K]
__device__ __align__(16) uint16_t g_wint [DIM*LDIMC];
__device__ __align__(16) uint16_t g_wqkvt[NLAYER*3*DIM*DIM];
__device__ __align__(16) uint16_t g_wot  [NLAYER*DIM*DIM];
__device__ __align__(16) uint16_t g_w1t  [NLAYER*FFN*DIM];
__device__ __align__(16) uint16_t g_w2t  [NLAYER*DIM*FFN];
// fp32 transposed flow weights
__device__ __align__(16) float g_wf1t[HID*KP1];
__device__ __align__(16) float g_wf2t[HID*HID];
__device__ __align__(16) float g_wf3t[LDIMC*HID];
// grid barrier state
__device__ unsigned g_bar_cnt = 0;
__device__ unsigned g_bar_gen = 0;

// ---------------- helpers ----------------
__device__ __forceinline__ float gelu_tanh(float x) {
    const float c = 0.7978845608028654f;
    float t = c * (x + 0.044715f * x * x * x);
    return 0.5f * x * (1.0f + tanhf(t));
}
__device__ __forceinline__ float silu(float x) { return x / (1.0f + __expf(-x)); }
__device__ __forceinline__ uint32_t pack_bf2(float a, float b) {
    __nv_bfloat162 h2 = __floats2bfloat162_rn(a, b);
    return *(uint32_t*)&h2;
}
__device__ __forceinline__ uint16_t bf16u(float a) {
    __nv_bfloat16 h = __float2bfloat16_rn(a);
    return *(uint16_t*)&h;
}
__device__ __forceinline__ void cp_async16(void* smem_dst, const void* gmem_src) {
    uint32_t s = (uint32_t)__cvta_generic_to_shared(smem_dst);
    asm volatile("cp.async.cg.shared.global [%0], [%1], 16;\n" :: "r"(s), "l"(gmem_src));
}
__device__ __forceinline__ int swz(int c) { return c + (c >> 4); }
#define LDSM_X4(r0, r1, r2, r3, addr) \
    asm volatile("ldmatrix.sync.aligned.m8n8.x4.shared.b16 {%0,%1,%2,%3}, [%4];" \
                 : "=r"(r0), "=r"(r1), "=r"(r2), "=r"(r3) : "r"(addr))

// ---------------- prep kernels ----------------
__global__ void tconv_kernel(const float* __restrict__ src, uint16_t* __restrict__ dst,
                             int K, int N) {
    __shared__ float tile[32][65];
    const float* s = src + (size_t)blockIdx.z * K * N;
    uint16_t* d    = dst + (size_t)blockIdx.z * K * N;
    int k0 = blockIdx.y * 64, n0 = blockIdx.x * 32;
    int tx = threadIdx.x, ty = threadIdx.y;
    #pragma unroll
    for (int i = 0; i < 8; i++) {
        int kk = ty + i * 8;
        tile[tx][kk] = s[(size_t)(k0 + kk) * N + n0 + tx];
    }
    __syncthreads();
    #pragma unroll
    for (int i = 0; i < 4; i++) {
        int nn = ty + i * 8;
        uint32_t p = pack_bf2(tile[nn][2 * tx], tile[nn][2 * tx + 1]);
        *(uint32_t*)&d[(size_t)(n0 + nn) * K + k0 + 2 * tx] = p;
    }
}
__global__ void zero_kernel(float* __restrict__ p, int n) {
    int i = blockIdx.x * blockDim.x + threadIdx.x;
    if (i < n) p[i] = 0.f;
}
__global__ void transpose_kernel(const float* __restrict__ src, float* __restrict__ dst,
                                 int R, int C, int dstride) {
    __shared__ float tile[32][33];
    int c0 = blockIdx.x * 32, r0 = blockIdx.y * 32;
    int tx = threadIdx.x, ty = threadIdx.y;
    #pragma unroll
    for (int i = 0; i < 4; i++) {
        int rr = r0 + ty + i * 8, cc = c0 + tx;
        if (rr < R && cc < C) tile[ty + i * 8][tx] = src[(size_t)rr * C + cc];
    }
    __syncthreads();
    #pragma unroll
    for (int i = 0; i < 4; i++) {
        int cc = c0 + ty + i * 8, rr = r0 + tx;
        if (cc < C && rr < R) dst[(size_t)cc * dstride + rr] = tile[tx][ty + i * 8];
    }
}

__global__ void nanfix_kernel(const float* __restrict__ seq,
                              const float* __restrict__ bos,
                              uint16_t* __restrict__ out, int n) {
    int i = blockIdx.x * blockDim.x + threadIdx.x;
    if (i < n) {
        float v = seq[i];
        v = (v != v) ? bos[i & (LDIMC - 1)] : v;
        out[i] = bf16u(v);
    }
}

// ---------------- fused concat + LayerNorm ----------------
__global__ void __launch_bounds__(256) concat_ln_kernel(
        const float* __restrict__ text, const float* __restrict__ x,
        float* __restrict__ h, uint16_t* __restrict__ lnout,
        const float* __restrict__ g, const float* __restrict__ bta) {
    int row = blockIdx.x, tid = threadIdx.x;
    int b = row / TTOT, t = row - b * TTOT;
    float4 v;
    if (t < TTXT)
        v = ((const float4*)text)[(size_t)(b * TTXT + t) * 256 + tid];
    else
        v = ((const float4*)x)[(size_t)(b * TSEQ + (t - TTXT)) * 256 + tid];
    ((float4*)(h + (size_t)row * DIM))[tid] = v;

    float s  = v.x + v.y + v.z + v.w;
    float ss = v.x*v.x + v.y*v.y + v.z*v.z + v.w*v.w;
    #pragma unroll
    for (int o = 16; o; o >>= 1) {
        s  += __shfl_xor_sync(0xffffffffu, s,  o);
        ss += __shfl_xor_sync(0xffffffffu, ss, o);
    }
    __shared__ float sh[16];
    int w = tid >> 5, l = tid & 31;
    if (l == 0) { sh[w] = s; sh[8 + w] = ss; }
    __syncthreads();
    float S = 0.f, SS = 0.f;
    #pragma unroll
    for (int i = 0; i < 8; i++) { S += sh[i]; SS += sh[8 + i]; }
    float mean = S * (1.0f / DIM);
    float var  = SS * (1.0f / DIM) - mean * mean;
    float rs   = rsqrtf(var + 1e-5f);
    float4 gg = ((const float4*)g)[tid];
    float4 bb = ((const float4*)bta)[tid];
    uint2 o2;
    o2.x = pack_bf2((v.x - mean) * rs * gg.x + bb.x, (v.y - mean) * rs * gg.y + bb.y);
    o2.y = pack_bf2((v.z - mean) * rs * gg.z + bb.z, (v.w - mean) * rs * gg.w + bb.w);
    ((uint2*)(lnout + (size_t)row * DIM))[tid] = o2;
}

// ---------------- combine 4 split-K partials + optional fused LN ----------------
__global__ void __launch_bounds__(256) combine_ln_kernel(
        const float* __restrict__ p, const float* __restrict__ bias,
        float* __restrict__ h,
        const float* __restrict__ g, const float* __restrict__ bta,
        uint16_t* __restrict__ lnout, int do_ln) {
    int row = blockIdx.x, tid = threadIdx.x;
    size_t off = (size_t)row * DIM;
    const size_t stride = (size_t)MROWS * DIM;
    float4 a0 = ((const float4*)(p + off))[tid];
    float4 a1 = ((const float4*)(p + stride + off))[tid];
    float4 a2 = ((const float4*)(p + 2 * stride + off))[tid];
    float4 a3 = ((const float4*)(p + 3 * stride + off))[tid];
    float4 r  = ((const float4*)(h + off))[tid];
    float4 bb = ((const float4*)bias)[tid];
    r.x += (a0.x + a1.x) + (a2.x + a3.x) + bb.x;
    r.y += (a0.y + a1.y) + (a2.y + a3.y) + bb.y;
    r.z += (a0.z + a1.z) + (a2.z + a3.z) + bb.z;
    r.w += (a0.w + a1.w) + (a2.w + a3.w) + bb.w;
    ((float4*)(h + off))[tid] = r;
    if (!do_ln) return;
    float s  = r.x + r.y + r.z + r.w;
    float ss = r.x*r.x + r.y*r.y + r.z*r.z + r.w*r.w;
    #pragma unroll
    for (int o = 16; o; o >>= 1) {
        s  += __shfl_xor_sync(0xffffffffu, s,  o);
        ss += __shfl_xor_sync(0xffffffffu, ss, o);
    }
    __shared__ float sh[16];
    int w = tid >> 5, l = tid & 31;
    if (l == 0) { sh[w] = s; sh[8 + w] = ss; }
    __syncthreads();
    float S = 0.f, SS = 0.f;
    #pragma unroll
    for (int i = 0; i < 8; i++) { S += sh[i]; SS += sh[8 + i]; }
    float mean = S * (1.0f / DIM);
    float var  = SS * (1.0f / DIM) - mean * mean;
    float rs   = rsqrtf(var + 1e-5f);
    float4 gg = ((const float4*)g)[tid];
    float4 b2 = ((const float4*)bta)[tid];
    uint2 o2;
    o2.x = pack_bf2((r.x - mean) * rs * gg.x + b2.x, (r.y - mean) * rs * gg.y + b2.y);
    o2.y = pack_bf2((r.z - mean) * rs * gg.z + b2.z, (r.w - mean) * rs * gg.w + b2.w);
    ((uint2*)(lnout + off))[tid] = o2;
}

// ---------------- bf16 tensor-core GEMM (mma.sync + ldmatrix, 2-stage cp.async) ----------------
#define BKT 64
#define ASTR 72
#define ATILE (128*ASTR)
#define STAGE_ELEMS (2*ATILE)
#define STAGE_BYTES (STAGE_ELEMS*2)
#define TG_SMEM (2*STAGE_BYTES)       // 73728 bytes

__global__ void __launch_bounds__(256, 2) tgemm_bf16(
        const uint16_t* __restrict__ A, int lda,
        const uint16_t* __restrict__ Bt, int ldb,
        const float* __restrict__ bias,
        float* __restrict__ Cf, uint16_t* __restrict__ Cb,
        int M, int N, int K, int epi) {
    extern __shared__ uint16_t smb[];

    const int tid = threadIdx.x;
    const int bm = blockIdx.y * 128, bn = blockIdx.x * 128;
    const int koff = blockIdx.z * K;
    const int warp = tid >> 5, lane = tid & 31;
    const int wm = (warp & 3) * 32;
    const int wn = (warp >> 2) * 64;
    const int g  = lane >> 2, t = lane & 3;

    const uint16_t* Ab0 = A  + (size_t)bm * lda + koff;
    const uint16_t* Bb0 = Bt + (size_t)bn * ldb + koff;

    auto loadStage = [&](int kt, int stage) {
        uint16_t* As = smb + stage * STAGE_ELEMS;
        uint16_t* Bs = As + ATILE;
        #pragma unroll
        for (int i = 0; i < 4; i++) {
            int idx = tid + i * 256;
            int r = idx >> 3, c = idx & 7;
            cp_async16(As + r * ASTR + c * 8, Ab0 + (size_t)r * lda + kt * BKT + c * 8);
            cp_async16(Bs + r * ASTR + c * 8, Bb0 + (size_t)r * ldb + kt * BKT + c * 8);
        }
        asm volatile("cp.async.commit_group;\n" ::);
    };

    float acc[2][8][4];
    #pragma unroll
    for (int i = 0; i < 2; i++)
        #pragma unroll
        for (int j = 0; j < 8; j++)
            #pragma unroll
            for (int q = 0; q < 4; q++) acc[i][j][q] = 0.f;

    const uint32_t smemBase = (uint32_t)__cvta_generic_to_shared(smb);
    const int arow = lane & 15, ahalf = lane >> 4;
    const uint32_t aoff0 = (uint32_t)(((wm      + arow) * ASTR + ahalf * 8) * 2);
    const uint32_t aoff1 = (uint32_t)(((wm + 16 + arow) * ASTR + ahalf * 8) * 2);
    uint32_t boff[4];
    #pragma unroll
    for (int p = 0; p < 4; p++)
        boff[p] = (uint32_t)(((wn + p * 16 + arow) * ASTR + ahalf * 8) * 2) + ATILE * 2;

    const int nk = K / BKT;
    loadStage(0, 0);

    for (int kt = 0; kt < nk; kt++) {
        if (kt + 1 < nk) {
            loadStage(kt + 1, (kt + 1) & 1);
            asm volatile("cp.async.wait_group 1;\n" ::);
        } else {
            asm volatile("cp.async.wait_group 0;\n" ::);
        }
        __syncthreads();

        const uint32_t st = smemBase + (kt & 1) * STAGE_BYTES;

        #pragma unroll
        for (int ks = 0; ks < 4; ks++) {
            const uint32_t kadd = ks * 32;
            uint32_t af[2][4], bw[4][4];
            LDSM_X4(af[0][0], af[0][1], af[0][2], af[0][3], st + aoff0 + kadd);
            LDSM_X4(af[1][0], af[1][1], af[1][2], af[1][3], st + aoff1 + kadd);
            #pragma unroll
            for (int p = 0; p < 4; p++)
                LDSM_X4(bw[p][0], bw[p][1], bw[p][2], bw[p][3], st + boff[p] + kadd);
            #pragma unroll
            for (int mt = 0; mt < 2; mt++)
                #pragma unroll
                for (int nt = 0; nt < 8; nt++) {
                    uint32_t b0 = bw[nt >> 1][nt & 1];
                    uint32_t b1 = bw[nt >> 1][2 + (nt & 1)];
                    asm volatile(
                        "mma.sync.aligned.m16n8k16.row.col.f32.bf16.bf16.f32 "
                        "{%0,%1,%2,%3}, {%4,%5,%6,%7}, {%8,%9}, {%0,%1,%2,%3};\n"
                        : "+f"(acc[mt][nt][0]), "+f"(acc[mt][nt][1]),
                          "+f"(acc[mt][nt][2]), "+f"(acc[mt][nt][3])
                        : "r"(af[mt][0]), "r"(af[mt][1]), "r"(af[mt][2]), "r"(af[mt][3]),
                          "r"(b0), "r"(b1));
                }
        }
        __syncthreads();
    }

    float* Cout = (epi == 3) ? (Cf + (size_t)blockIdx.z * M * N) : Cf;
    #pragma unroll
    for (int mt = 0; mt < 2; mt++) {
        #pragma unroll
        for (int nt = 0; nt < 8; nt++) {
            int c = bn + wn + nt * 8 + t * 2;
            float bx = 0.f, by = 0.f;
            if (epi != 3) { bx = bias[c]; by = bias[c + 1]; }
            #pragma unroll
            for (int rr = 0; rr < 2; rr++) {
                int gm = bm + wm + mt * 16 + g + rr * 8;
                size_t off = (size_t)gm * N + c;
                float vx = acc[mt][nt][rr * 2 + 0] + bx;
                float vy = acc[mt][nt][rr * 2 + 1] + by;
                if (epi == 1) {
                    *(uint32_t*)&Cb[off] = pack_bf2(gelu_tanh(vx), gelu_tanh(vy));
                } else {
                    *(float2*)&Cout[off] = make_float2(vx, vy);
                }
            }
        }
    }
}

// ---------------- causal attention (fp32 in, bf16 out) ----------------
__global__ void __launch_bounds__(256) attn_kernel(
        const float* __restrict__ qkv, uint16_t* __restrict__ o) {
    const int qt = blockIdx.x, hh = blockIdx.y, b = blockIdx.z;
    const int tid = threadIdx.x;
    const int ql = tid >> 2, part = tid & 3;
    const int q  = qt * 64 + ql;

    __shared__ float Ks[64 * 68];
    __shared__ float Vs[64 * 68];

    float qreg[16], acc[16];
    const float* qp = qkv + (size_t)(b * TTOT + q) * (3 * DIM) + hh * HDIM + part * 16;
    #pragma unroll
    for (int i = 0; i < 4; i++) {
        float4 v = ((const float4*)qp)[i];
        qreg[4*i+0] = v.x; qreg[4*i+1] = v.y; qreg[4*i+2] = v.z; qreg[4*i+3] = v.w;
    }
    #pragma unroll
    for (int d = 0; d < 16; d++) acc[d] = 0.f;
    float mrun = -1e30f, lrun = 0.f;

    const int nkt = qt + 1;
    for (int kt = 0; kt < nkt; kt++) {
        {
            int r = tid >> 2, c = (tid & 3) * 16;
            const float* kp = qkv + (size_t)(b * TTOT + kt * 64 + r) * (3 * DIM)
                              + DIM + hh * HDIM + c;
            const float* vp = kp + DIM;
            #pragma unroll
            for (int i = 0; i < 4; i++) {
                float4 kv = ((const float4*)kp)[i];
                float4 vv = ((const float4*)vp)[i];
                int cb = c + i * 4;
                Ks[r * 68 + swz(cb+0)] = kv.x; Ks[r * 68 + swz(cb+1)] = kv.y;
                Ks[r * 68 + swz(cb+2)] = kv.z; Ks[r * 68 + swz(cb+3)] = kv.w;
                Vs[r * 68 + swz(cb+0)] = vv.x; Vs[r * 68 + swz(cb+1)] = vv.y;
                Vs[r * 68 + swz(cb+2)] = vv.z; Vs[r * 68 + swz(cb+3)] = vv.w;
            }
        }
        __syncthreads();

        const int pbase = part * 17;
        for (int j0 = 0; j0 < 64; j0 += 4) {
            float sj[4];
            #pragma unroll
            for (int jj = 0; jj < 4; jj++) {
                const float* kr = &Ks[(j0 + jj) * 68 + pbase];
                float s = 0.f;
                #pragma unroll
                for (int d = 0; d < 16; d++) s = fmaf(qreg[d], kr[d], s);
                s += __shfl_xor_sync(0xffffffffu, s, 1);
                s += __shfl_xor_sync(0xffffffffu, s, 2);
                s *= 0.125f;
                int kg = kt * 64 + j0 + jj;
                sj[jj] = (kg <= q) ? s : -1e30f;
            }
            float tmax = fmaxf(fmaxf(sj[0], sj[1]), fmaxf(sj[2], sj[3]));
            if (tmax > mrun) {
                float corr = __expf(mrun - tmax);
                lrun *= corr;
                #pragma unroll
                for (int d = 0; d < 16; d++) acc[d] *= corr;
                mrun = tmax;
            }
            float pm = __expf(sj[part] - mrun);
            float p0 = __shfl_sync(0xffffffffu, pm, 0, 4);
            float p1 = __shfl_sync(0xffffffffu, pm, 1, 4);
            float p2 = __shfl_sync(0xffffffffu, pm, 2, 4);
            float p3 = __shfl_sync(0xffffffffu, pm, 3, 4);
            lrun += p0 + p1 + p2 + p3;
            const float* vr0 = &Vs[(j0 + 0) * 68 + pbase];
            const float* vr1 = &Vs[(j0 + 1) * 68 + pbase];
            const float* vr2 = &Vs[(j0 + 2) * 68 + pbase];
            const float* vr3 = &Vs[(j0 + 3) * 68 + pbase];
            #pragma unroll
            for (int d = 0; d < 16; d++) {
                float a = acc[d];
                a = fmaf(p0, vr0[d], a);
                a = fmaf(p1, vr1[d], a);
                a = fmaf(p2, vr2[d], a);
                a = fmaf(p3, vr3[d], a);
                acc[d] = a;
            }
        }
        __syncthreads();
    }

    float inv = 1.0f / lrun;
    uint16_t* op = o + (size_t)(b * TTOT + q) * DIM + hh * HDIM + part * 16;
    uint4 u0, u1;
    u0.x = pack_bf2(acc[0]*inv,  acc[1]*inv);  u0.y = pack_bf2(acc[2]*inv,  acc[3]*inv);
    u0.z = pack_bf2(acc[4]*inv,  acc[5]*inv);  u0.w = pack_bf2(acc[6]*inv,  acc[7]*inv);
    u1.x = pack_bf2(acc[8]*inv,  acc[9]*inv);  u1.y = pack_bf2(acc[10]*inv, acc[11]*inv);
    u1.z = pack_bf2(acc[12]*inv, acc[13]*inv); u1.w = pack_bf2(acc[14]*inv, acc[15]*inv);
    ((uint4*)op)[0] = u0;
    ((uint4*)op)[1] = u1;
}

// ---------------- finalize ----------------
__global__ void __launch_bounds__(256) finalize_kernel(
        const float* __restrict__ h, const float* __restrict__ noise,
        const float* __restrict__ ong, const float* __restrict__ onb,
        const float* __restrict__ Weos, const float* __restrict__ beos,
        float* __restrict__ last, float* __restrict__ cur,
        float* __restrict__ out, int out_size) {
    int b = blockIdx.x, tid = threadIdx.x;
    float4 v = ((const float4*)(h + (size_t)(b * TTOT + TTOT - 1) * DIM))[tid];
    float s  = v.x + v.y + v.z + v.w;
    float ss = v.x*v.x + v.y*v.y + v.z*v.z + v.w*v.w;
    #pragma unroll
    for (int o = 16; o; o >>= 1) {
        s  += __shfl_xor_sync(0xffffffffu, s,  o);
        ss += __shfl_xor_sync(0xffffffffu, ss, o);
    }
    __shared__ float sh[16];
    int w = tid >> 5, l = tid & 31;
    if (l == 0) { sh[w] = s; sh[8 + w] = ss; }
    __syncthreads();
    float S = 0.f, SS = 0.f;
    #pragma unroll
    for (int i = 0; i < 8; i++) { S += sh[i]; SS += sh[8 + i]; }
    float mean = S * (1.0f / DIM);
    float var  = SS * (1.0f / DIM) - mean * mean;
    float rs   = rsqrtf(var + 1e-5f);
    float4 gg = ((const float4*)ong)[tid];
    float4 bb = ((const float4*)onb)[tid];
    float4 nv;
    nv.x = (v.x - mean) * rs * gg.x + bb.x;
    nv.y = (v.y - mean) * rs * gg.y + bb.y;
    nv.z = (v.z - mean) * rs * gg.z + bb.z;
    nv.w = (v.w - mean) * rs * gg.w + bb.w;
    ((float4*)(last + (size_t)b * DIM))[tid] = nv;
    float4 we = ((const float4*)Weos)[tid];
    float p = nv.x*we.x + nv.y*we.y + nv.z*we.z + nv.w*we.w;
    __shared__ float red[256];
    red[tid] = p;
    __syncthreads();
    for (int st = 128; st; st >>= 1) {
        if (tid < st) red[tid] += red[tid + st];
        __syncthreads();
    }
    if (tid == 0 && (1024 + b) < out_size) {
        float e = red[0] + beos[0];
        out[1024 + b] = (e > 0.5f) ? 1.0f : 0.0f;
    }
    if (tid < LDIMC) cur[b * LDIMC + tid] = noise[b * LDIMC + tid];
}

// ---------------- persistent flow decoder ----------------
#define FLOW_BLOCKS 128
#define FLOW_SMEM ((8*KP1 + 8*HID)*4)

__device__ __forceinline__ void gbar(unsigned expect) {
    __syncthreads();
    if (threadIdx.x == 0) {
        __threadfence();
        unsigned a = atomicAdd(&g_bar_cnt, 1u);
        if (a == FLOW_BLOCKS - 1) {
            atomicExch(&g_bar_cnt, 0u);
            __threadfence();
            atomicAdd(&g_bar_gen, 1u);
        } else {
            while (*((volatile unsigned*)&g_bar_gen) != expect) { }
            __threadfence();
        }
    }
    __syncthreads();
}

__global__ void __launch_bounds__(256) flow_all_kernel(
        const float* __restrict__ last, float* __restrict__ cur,
        const float* __restrict__ Wf1t, const float* __restrict__ bf1,
        const float* __restrict__ Wf2t, const float* __restrict__ bf2,
        const float* __restrict__ Wf3t, const float* __restrict__ bf3,
        float* __restrict__ f1, float* __restrict__ f2) {
    extern __shared__ float shf[];
    float* xs1 = shf;
    float* xs2 = shf + 8 * KP1;
    const int tid = threadIdx.x, blk = blockIdx.x;
    const int warp = tid >> 5, lane = tid & 31;

    unsigned gen0 = *((volatile unsigned*)&g_bar_gen);
    unsigned bc = 0;

    for (int i = tid; i < 8 * 1024; i += 256) {
        int m = i >> 10, k = i & 1023;
        xs1[m * KP1 + k] = last[m * 1024 + k];
    }
    if (tid < 48) {
        int m = tid / 6, k = KF1 + tid % 6;
        xs1[m * KP1 + k] = 0.f;
    }

    for (int step = 0; step < NSTEPS; step++) {
        float sv = (float)step / NSTEPS;
        float tv = (float)(step + 1) / NSTEPS;
        for (int i = tid; i < 8 * LDIMC; i += 256) {
            int m = i >> 7, k = i & 127;
            xs1[m * KP1 + 1026 + k] = cur[i];
        }
        if (tid < 16) {
            int m = tid >> 1;
            xs1[m * KP1 + 1024 + (tid & 1)] = (tid & 1) ? tv : sv;
        }
        __syncthreads();

        {
            int n = blk * 8 + warp;
            const float* wp = Wf1t + (size_t)n * KP1;
            float acc[8] = {0,0,0,0,0,0,0,0};
            for (int k0 = lane * 4; k0 < KP1; k0 += 128) {
                float4 w4 = *(const float4*)&wp[k0];
                #pragma unroll
                for (int m = 0; m < 8; m++) {
                    float4 x4 = *(const float4*)&xs1[m * KP1 + k0];
                    acc[m] += w4.x*x4.x + w4.y*x4.y + w4.z*x4.z + w4.w*x4.w;
                }
            }
            #pragma unroll
            for (int m = 0; m < 8; m++) {
                float v = acc[m];
                #pragma unroll
                for (int o2 = 16; o2; o2 >>= 1) v += __shfl_xor_sync(0xffffffffu, v, o2);
                acc[m] = v;
            }
            if (lane == 0) {
                float bn = bf1[n];
                #pragma unroll
                for (int m = 0; m < 8; m++) f1[m * HID + n] = silu(acc[m] + bn);
            }
        }
        gbar(gen0 + ++bc);

        for (int i = tid * 4; i < 8 * HID; i += 1024)
            *(float4*)&xs2[i] = *(const float4*)&f1[i];
        __syncthreads();
        {
            int n = blk * 8 + warp;
            const float* wp = Wf2t + (size_t)n * HID;
            float acc[8] = {0,0,0,0,0,0,0,0};
            for (int k0 = lane * 4; k0 < HID; k0 += 128) {
                float4 w4 = *(const float4*)&wp[k0];
                #pragma unroll
                for (int m = 0; m < 8; m++) {
                    float4 x4 = *(const float4*)&xs2[m * HID + k0];
                    acc[m] += w4.x*x4.x + w4.y*x4.y + w4.z*x4.z + w4.w*x4.w;
                }
            }
            #pragma unroll
            for (int m = 0; m < 8; m++) {
                float v = acc[m];
                #pragma unroll
                for (int o2 = 16; o2; o2 >>= 1) v += __shfl_xor_sync(0xffffffffu, v, o2);
                acc[m] = v;
            }
            if (lane == 0) {
                float bn = bf2[n];
                #pragma unroll
                for (int m = 0; m < 8; m++) f2[m * HID + n] = silu(acc[m] + bn);
            }
        }
        gbar(gen0 + ++bc);

        if (blk < 16) {
            for (int i = tid * 4; i < 8 * HID; i += 1024)
                *(float4*)&xs2[i] = *(const float4*)&f2[i];
            __syncthreads();
            int n = blk * 8 + warp;
            const float* wp = Wf3t + (size_t)n * HID;
            float acc[8] = {0,0,0,0,0,0,0,0};
            for (int k0 = lane * 4; k0 < HID; k0 += 128) {
                float4 w4 = *(const float4*)&wp[k0];
                #pragma unroll
                for (int m = 0; m < 8; m++) {
                    float4 x4 = *(const float4*)&xs2[m * HID + k0];
                    acc[m] += w4.x*x4.x + w4.y*x4.y + w4.z*x4.z + w4.w*x4.w;
                }
            }
            #pragma unroll
            for (int m = 0; m < 8; m++) {
                float v = acc[m];
                #pragma unroll
                for (int o2 = 16; o2; o2 >>= 1) v += __shfl_xor_sync(0xffffffffu, v, o2);
                acc[m] = v;
            }
            if (lane == 0) {
                float bn = bf3[n];
                #pragma unroll
                for (int m = 0; m < 8; m++)
                    cur[m * LDIMC + n] += (acc[m] + bn) * (1.0f / NSTEPS);
            }
        }
        gbar(gen0 + ++bc);
    }
}

__global__ void writeout_kernel(const float* __restrict__ cur,
                                float* __restrict__ out, int out_size) {
    int i = blockIdx.x * blockDim.x + threadIdx.x;
    if (i >= out_size) return;
    if (i < 1024)       out[i] = cur[i];
    else if (i >= 1032) out[i] = 0.0f;
}

// ---------------- host orchestration ----------------
extern "C" void kernel_launch(void* const* d_in, const int* in_sizes, int n_in,
                              void* d_out, int out_size) {
    const float* seq   = (const float*)d_in[0];
    const float* text  = (const float*)d_in[1];
    const float* noise = (const float*)d_in[2];
    const float* bos   = (const float*)d_in[4];
    const float* W_in  = (const float*)d_in[5];
    const float* b_in  = (const float*)d_in[6];
    const float* ln1g  = (const float*)d_in[7];
    const float* ln1b  = (const float*)d_in[8];
    const float* Wqkv  = (const float*)d_in[9];
    const float* bqkv  = (const float*)d_in[10];
    const float* Wo    = (const float*)d_in[11];
    const float* bo    = (const float*)d_in[12];
    const float* ln2g  = (const float*)d_in[13];
    const float* ln2b  = (const float*)d_in[14];
    const float* W1    = (const float*)d_in[15];
    const float* b1    = (const float*)d_in[16];
    const float* W2    = (const float*)d_in[17];
    const float* b2    = (const float*)d_in[18];
    const float* ong   = (const float*)d_in[19];
    const float* onb   = (const float*)d_in[20];
    const float* Weos  = (const float*)d_in[21];
    const float* beos  = (const float*)d_in[22];
    const float* Wf1   = (const float*)d_in[23];
    const float* bf1   = (const float*)d_in[24];
    const float* Wf2   = (const float*)d_in[25];
    const float* bf2   = (const float*)d_in[26];
    const float* Wf3   = (const float*)d_in[27];
    const float* bf3   = (const float*)d_in[28];
    float* out = (float*)d_out;

    uint16_t *p_seqb, *p_tmpb, *p_attb, *p_midb;
    uint16_t *p_wint, *p_wqkvt, *p_wot, *p_w1t, *p_w2t;
    float *p_x, *p_h, *p_qkv, *p_last, *p_cur, *p_f1, *p_f2, *p_p01;
    float *p_wf1t, *p_wf2t, *p_wf3t;
    cudaGetSymbolAddress((void**)&p_seqb,  g_seqb);
    cudaGetSymbolAddress((void**)&p_tmpb,  g_tmpb);
    cudaGetSymbolAddress((void**)&p_attb,  g_attb);
    cudaGetSymbolAddress((void**)&p_midb,  g_midb);
    cudaGetSymbolAddress((void**)&p_wint,  g_wint);
    cudaGetSymbolAddress((void**)&p_wqkvt, g_wqkvt);
    cudaGetSymbolAddress((void**)&p_wot,   g_wot);
    cudaGetSymbolAddress((void**)&p_w1t,   g_w1t);
    cudaGetSymbolAddress((void**)&p_w2t,   g_w2t);
    cudaGetSymbolAddress((void**)&p_x,     g_x);
    cudaGetSymbolAddress((void**)&p_h,     g_h);
    cudaGetSymbolAddress((void**)&p_qkv,   g_qkv);
    cudaGetSymbolAddress((void**)&p_last,  g_last);
    cudaGetSymbolAddress((void**)&p_cur,   g_cur);
    cudaGetSymbolAddress((void**)&p_f1,    g_f1);
    cudaGetSymbolAddress((void**)&p_f2,    g_f2);
    cudaGetSymbolAddress((void**)&p_p01,   g_p01);
    cudaGetSymbolAddress((void**)&p_wf1t,  g_wf1t);
    cudaGetSymbolAddress((void**)&p_wf2t,  g_wf2t);
    cudaGetSymbolAddress((void**)&p_wf3t,  g_wf3t);

    cudaFuncSetAttribute(tgemm_bf16,
                         cudaFuncAttributeMaxDynamicSharedMemorySize, TG_SMEM);
    cudaFuncSetAttribute(flow_all_kernel,
                         cudaFuncAttributeMaxDynamicSharedMemorySize, FLOW_SMEM);

    dim3 tb(32, 8);
    int nseq = BDIM * TSEQ * LDIMC;

    tconv_kernel<<<dim3(DIM/32,  LDIMC/64, 1),      tb>>>(W_in, p_wint,  LDIMC, DIM);
    nanfix_kernel<<<(nseq + 255)/256, 256>>>(seq, bos, p_seqb, nseq);
    tconv_kernel<<<dim3(3*DIM/32, DIM/64, NLAYER),  tb>>>(Wqkv, p_wqkvt, DIM, 3*DIM);
    tgemm_bf16<<<dim3(DIM/128, (BDIM*TSEQ)/128, 1), 256, TG_SMEM>>>(
        p_seqb, LDIMC, p_wint, LDIMC, b_in, p_x, nullptr, BDIM*TSEQ, DIM, LDIMC, 0);
    concat_ln_kernel<<<MROWS, 256>>>(text, p_x, p_h, p_tmpb, ln1g, ln1b);
    tgemm_bf16<<<dim3(3*DIM/128, MROWS/128, 1), 256, TG_SMEM>>>(
        p_tmpb, DIM, p_wqkvt, DIM, bqkv, p_qkv, nullptr, MROWS, 3*DIM, DIM, 0);

    // remaining weight prep
    tconv_kernel<<<dim3(DIM/32,  DIM/64, NLAYER),   tb>>>(Wo,   p_wot,   DIM, DIM);
    tconv_kernel<<<dim3(FFN/32,  DIM/64, NLAYER),   tb>>>(W1,   p_w1t,   DIM, FFN);
    tconv_kernel<<<dim3(DIM/32,  FFN/64, NLAYER),   tb>>>(W2,   p_w2t,   FFN, DIM);
    zero_kernel<<<(HID*KP1 + 255)/256, 256>>>(p_wf1t, HID*KP1);
    transpose_kernel<<<dim3((HID+31)/32, (KF1+31)/32), tb>>>(Wf1, p_wf1t, KF1, HID, KP1);
    transpose_kernel<<<dim3((HID+31)/32, (HID+31)/32), tb>>>(Wf2, p_wf2t, HID, HID, HID);
    transpose_kernel<<<dim3((LDIMC+31)/32, (HID+31)/32), tb>>>(Wf3, p_wf3t, HID, LDIMC, HID);

    // transformer layers (QKV for layer l+1 launched at end of layer l)
    for (int l = 0; l < NLAYER; l++) {
        attn_kernel<<<dim3(TTOT/64, HEADS, BDIM), 256>>>(p_qkv, p_attb);
        // Wo: split-K=4 (klen 256) -> grid 640, better wave utilization
        tgemm_bf16<<<dim3(DIM/128, MROWS/128, KSLICES), 256, TG_SMEM>>>(
            p_attb, DIM, p_wot + (size_t)l*DIM*DIM, DIM,
            nullptr, p_p01, nullptr, MROWS, DIM, 1024/KSLICES, 3);
        combine_ln_kernel<<<MROWS, 256>>>(
            p_p01, bo + l*DIM, p_h,
            ln2g + l*DIM, ln2b + l*DIM, p_tmpb, 1);
        tgemm_bf16<<<dim3(FFN/128, MROWS/128, 1), 256, TG_SMEM>>>(
            p_tmpb, DIM, p_w1t + (size_t)l*FFN*DIM, DIM,
            b1 + l*FFN, nullptr, p_midb, MROWS, FFN, DIM, 1);
        // W2: split-K=4 (klen 1024) -> grid 640
        tgemm_bf16<<<dim3(DIM/128, MROWS/128, KSLICES), 256, TG_SMEM>>>(
            p_midb, FFN, p_w2t + (size_t)l*DIM*FFN, FFN,
            nullptr, p_p01, nullptr, MROWS, DIM, 4096/KSLICES, 3);
        if (l < NLAYER - 1) {
            combine_ln_kernel<<<MROWS, 256>>>(
                p_p01, b2 + l*DIM, p_h,
                ln1g + (l+1)*DIM, ln1b + (l+1)*DIM, p_tmpb, 1);
            tgemm_bf16<<<dim3(3*DIM/128, MROWS/128, 1), 256, TG_SMEM>>>(
                p_tmpb, DIM, p_wqkvt + (size_t)(l+1)*3*DIM*DIM, DIM,
                bqkv + (l+1)*3*DIM, p_qkv, nullptr, MROWS, 3*DIM, DIM, 0);
        } else {
            combine_ln_kernel<<<MROWS, 256>>>(
                p_p01, b2 + l*DIM, p_h,
                nullptr, nullptr, nullptr, 0);
        }
    }

    // finalize
    finalize_kernel<<<BDIM, 256>>>(p_h, noise, ong, onb, Weos, beos,
                                   p_last, p_cur, out, out_size);

    // persistent flow decoder
    flow_all_kernel<<<FLOW_BLOCKS, 256, FLOW_SMEM>>>(
        p_last, p_cur, p_wf1t, bf1, p_wf2t, bf2, p_wf3t, bf3, p_f1, p_f2);

    // write output
    int ncov = out_size > 1024 ? out_size : 1024;
    writeout_kernel<<<(ncov + 255)/256, 256>>>(p_cur, out, out_size);
}

// round 12
// speedup vs baseline: 1.0560x; 1.0153x over previous
#include <cuda_runtime.h>
#include <cuda_bf16.h>
#include <math.h>
#include <stdint.h>

// ---------------- model constants ----------------
#define BDIM   8
#define TTXT   64
#define TSEQ   256
#define TTOT   320
#define MROWS  (BDIM*TTOT)    // 2560
#define DIM    1024
#define LDIMC  128
#define FFN    4096
#define HEADS  16
#define HDIM   64
#define NLAYER 4
#define HID    1024
#define KF1    1154
#define KP1    1160
#define NSTEPS 16
#define KSLICES 4

// ---------------- scratch ----------------
__device__ __align__(16) uint16_t g_seqb[BDIM*TSEQ*LDIMC];
__device__ __align__(16) float    g_x   [BDIM*TSEQ*DIM];
__device__ __align__(16) float    g_h   [MROWS*DIM];
__device__ __align__(16) uint16_t g_tmpb[MROWS*DIM];
__device__ __align__(16) uint16_t g_qkvb[MROWS*3*DIM];     // bf16 QKV
__device__ __align__(16) uint16_t g_attb[MROWS*DIM];
__device__ __align__(16) uint16_t g_midb[MROWS*FFN];
__device__ __align__(16) float    g_last[BDIM*DIM];
__device__ __align__(16) float    g_cur [BDIM*LDIMC];
__device__ __align__(16) float    g_f1  [BDIM*HID];
__device__ __align__(16) float    g_f2  [BDIM*HID];
__device__ __align__(16) float    g_p01 [KSLICES*MROWS*DIM];
// bf16 transposed weights  W^T [N][K]
__device__ __align__(16) uint16_t g_wint [DIM*LDIMC];
__device__ __align__(16) uint16_t g_wqkvt[NLAYER*3*DIM*DIM];
__device__ __align__(16) uint16_t g_wot  [NLAYER*DIM*DIM];
__device__ __align__(16) uint16_t g_w1t  [NLAYER*FFN*DIM];
__device__ __align__(16) uint16_t g_w2t  [NLAYER*DIM*FFN];
// fp32 transposed flow weights
__device__ __align__(16) float g_wf1t[HID*KP1];
__device__ __align__(16) float g_wf2t[HID*HID];
__device__ __align__(16) float g_wf3t[LDIMC*HID];
// grid barrier state
__device__ unsigned g_bar_cnt = 0;
__device__ unsigned g_bar_gen = 0;

// ---------------- helpers ----------------
__device__ __forceinline__ float gelu_tanh(float x) {
    const float c = 0.7978845608028654f;
    float t = c * (x + 0.044715f * x * x * x);
    return 0.5f * x * (1.0f + tanhf(t));
}
__device__ __forceinline__ float silu(float x) { return x / (1.0f + __expf(-x)); }
__device__ __forceinline__ uint32_t pack_bf2(float a, float b) {
    __nv_bfloat162 h2 = __floats2bfloat162_rn(a, b);
    return *(uint32_t*)&h2;
}
__device__ __forceinline__ uint16_t bf16u(float a) {
    __nv_bfloat16 h = __float2bfloat16_rn(a);
    return *(uint16_t*)&h;
}
__device__ __forceinline__ float2 unpack_bf2(uint32_t w) {
    __nv_bfloat162 h2 = *(__nv_bfloat162*)&w;
    return __bfloat1622float2(h2);
}
__device__ __forceinline__ void cp_async16(void* smem_dst, const void* gmem_src) {
    uint32_t s = (uint32_t)__cvta_generic_to_shared(smem_dst);
    asm volatile("cp.async.cg.shared.global [%0], [%1], 16;\n" :: "r"(s), "l"(gmem_src));
}
__device__ __forceinline__ int swz(int c) { return c + (c >> 4); }
#define LDSM_X4(r0, r1, r2, r3, addr) \
    asm volatile("ldmatrix.sync.aligned.m8n8.x4.shared.b16 {%0,%1,%2,%3}, [%4];" \
                 : "=r"(r0), "=r"(r1), "=r"(r2), "=r"(r3) : "r"(addr))

// ---------------- prep kernels ----------------
__global__ void tconv_kernel(const float* __restrict__ src, uint16_t* __restrict__ dst,
                             int K, int N) {
    __shared__ float tile[32][65];
    const float* s = src + (size_t)blockIdx.z * K * N;
    uint16_t* d    = dst + (size_t)blockIdx.z * K * N;
    int k0 = blockIdx.y * 64, n0 = blockIdx.x * 32;
    int tx = threadIdx.x, ty = threadIdx.y;
    #pragma unroll
    for (int i = 0; i < 8; i++) {
        int kk = ty + i * 8;
        tile[tx][kk] = s[(size_t)(k0 + kk) * N + n0 + tx];
    }
    __syncthreads();
    #pragma unroll
    for (int i = 0; i < 4; i++) {
        int nn = ty + i * 8;
        uint32_t p = pack_bf2(tile[nn][2 * tx], tile[nn][2 * tx + 1]);
        *(uint32_t*)&d[(size_t)(n0 + nn) * K + k0 + 2 * tx] = p;
    }
}
__global__ void zero_kernel(float* __restrict__ p, int n) {
    int i = blockIdx.x * blockDim.x + threadIdx.x;
    if (i < n) p[i] = 0.f;
}
__global__ void transpose_kernel(const float* __restrict__ src, float* __restrict__ dst,
                                 int R, int C, int dstride) {
    __shared__ float tile[32][33];
    int c0 = blockIdx.x * 32, r0 = blockIdx.y * 32;
    int tx = threadIdx.x, ty = threadIdx.y;
    #pragma unroll
    for (int i = 0; i < 4; i++) {
        int rr = r0 + ty + i * 8, cc = c0 + tx;
        if (rr < R && cc < C) tile[ty + i * 8][tx] = src[(size_t)rr * C + cc];
    }
    __syncthreads();
    #pragma unroll
    for (int i = 0; i < 4; i++) {
        int cc = c0 + ty + i * 8, rr = r0 + tx;
        if (cc < C && rr < R) dst[(size_t)cc * dstride + rr] = tile[tx][ty + i * 8];
    }
}

__global__ void nanfix_kernel(const float* __restrict__ seq,
                              const float* __restrict__ bos,
                              uint16_t* __restrict__ out, int n) {
    int i = blockIdx.x * blockDim.x + threadIdx.x;
    if (i < n) {
        float v = seq[i];
        v = (v != v) ? bos[i & (LDIMC - 1)] : v;
        out[i] = bf16u(v);
    }
}

// ---------------- fused concat + LayerNorm ----------------
__global__ void __launch_bounds__(256) concat_ln_kernel(
        const float* __restrict__ text, const float* __restrict__ x,
        float* __restrict__ h, uint16_t* __restrict__ lnout,
        const float* __restrict__ g, const float* __restrict__ bta) {
    int row = blockIdx.x, tid = threadIdx.x;
    int b = row / TTOT, t = row - b * TTOT;
    float4 v;
    if (t < TTXT)
        v = ((const float4*)text)[(size_t)(b * TTXT + t) * 256 + tid];
    else
        v = ((const float4*)x)[(size_t)(b * TSEQ + (t - TTXT)) * 256 + tid];
    ((float4*)(h + (size_t)row * DIM))[tid] = v;

    float s  = v.x + v.y + v.z + v.w;
    float ss = v.x*v.x + v.y*v.y + v.z*v.z + v.w*v.w;
    #pragma unroll
    for (int o = 16; o; o >>= 1) {
        s  += __shfl_xor_sync(0xffffffffu, s,  o);
        ss += __shfl_xor_sync(0xffffffffu, ss, o);
    }
    __shared__ float sh[16];
    int w = tid >> 5, l = tid & 31;
    if (l == 0) { sh[w] = s; sh[8 + w] = ss; }
    __syncthreads();
    float S = 0.f, SS = 0.f;
    #pragma unroll
    for (int i = 0; i < 8; i++) { S += sh[i]; SS += sh[8 + i]; }
    float mean = S * (1.0f / DIM);
    float var  = SS * (1.0f / DIM) - mean * mean;
    float rs   = rsqrtf(var + 1e-5f);
    float4 gg = ((const float4*)g)[tid];
    float4 bb = ((const float4*)bta)[tid];
    uint2 o2;
    o2.x = pack_bf2((v.x - mean) * rs * gg.x + bb.x, (v.y - mean) * rs * gg.y + bb.y);
    o2.y = pack_bf2((v.z - mean) * rs * gg.z + bb.z, (v.w - mean) * rs * gg.w + bb.w);
    ((uint2*)(lnout + (size_t)row * DIM))[tid] = o2;
}

// ---------------- combine 4 split-K partials + optional fused LN ----------------
__global__ void __launch_bounds__(256) combine_ln_kernel(
        const float* __restrict__ p, const float* __restrict__ bias,
        float* __restrict__ h,
        const float* __restrict__ g, const float* __restrict__ bta,
        uint16_t* __restrict__ lnout, int do_ln) {
    int row = blockIdx.x, tid = threadIdx.x;
    size_t off = (size_t)row * DIM;
    const size_t stride = (size_t)MROWS * DIM;
    float4 a0 = ((const float4*)(p + off))[tid];
    float4 a1 = ((const float4*)(p + stride + off))[tid];
    float4 a2 = ((const float4*)(p + 2 * stride + off))[tid];
    float4 a3 = ((const float4*)(p + 3 * stride + off))[tid];
    float4 r  = ((const float4*)(h + off))[tid];
    float4 bb = ((const float4*)bias)[tid];
    r.x += (a0.x + a1.x) + (a2.x + a3.x) + bb.x;
    r.y += (a0.y + a1.y) + (a2.y + a3.y) + bb.y;
    r.z += (a0.z + a1.z) + (a2.z + a3.z) + bb.z;
    r.w += (a0.w + a1.w) + (a2.w + a3.w) + bb.w;
    ((float4*)(h + off))[tid] = r;
    if (!do_ln) return;
    float s  = r.x + r.y + r.z + r.w;
    float ss = r.x*r.x + r.y*r.y + r.z*r.z + r.w*r.w;
    #pragma unroll
    for (int o = 16; o; o >>= 1) {
        s  += __shfl_xor_sync(0xffffffffu, s,  o);
        ss += __shfl_xor_sync(0xffffffffu, ss, o);
    }
    __shared__ float sh[16];
    int w = tid >> 5, l = tid & 31;
    if (l == 0) { sh[w] = s; sh[8 + w] = ss; }
    __syncthreads();
    float S = 0.f, SS = 0.f;
    #pragma unroll
    for (int i = 0; i < 8; i++) { S += sh[i]; SS += sh[8 + i]; }
    float mean = S * (1.0f / DIM);
    float var  = SS * (1.0f / DIM) - mean * mean;
    float rs   = rsqrtf(var + 1e-5f);
    float4 gg = ((const float4*)g)[tid];
    float4 b2 = ((const float4*)bta)[tid];
    uint2 o2;
    o2.x = pack_bf2((r.x - mean) * rs * gg.x + b2.x, (r.y - mean) * rs * gg.y + b2.y);
    o2.y = pack_bf2((r.z - mean) * rs * gg.z + b2.z, (r.w - mean) * rs * gg.w + b2.w);
    ((uint2*)(lnout + off))[tid] = o2;
}

// ---------------- bf16 tensor-core GEMM (mma.sync + ldmatrix, 2-stage cp.async) ----------------
// epi: 0 = bias->Cf(fp32) ; 1 = bias+gelu->Cb(bf16) ; 2 = bias->Cb(bf16) ; 3 = raw partial
#define BKT 64
#define ASTR 72
#define ATILE (128*ASTR)
#define STAGE_ELEMS (2*ATILE)
#define STAGE_BYTES (STAGE_ELEMS*2)
#define TG_SMEM (2*STAGE_BYTES)       // 73728 bytes

__global__ void __launch_bounds__(256, 2) tgemm_bf16(
        const uint16_t* __restrict__ A, int lda,
        const uint16_t* __restrict__ Bt, int ldb,
        const float* __restrict__ bias,
        float* __restrict__ Cf, uint16_t* __restrict__ Cb,
        int M, int N, int K, int epi) {
    extern __shared__ uint16_t smb[];

    const int tid = threadIdx.x;
    const int bm = blockIdx.y * 128, bn = blockIdx.x * 128;
    const int koff = blockIdx.z * K;
    const int warp = tid >> 5, lane = tid & 31;
    const int wm = (warp & 3) * 32;
    const int wn = (warp >> 2) * 64;
    const int g  = lane >> 2, t = lane & 3;

    const uint16_t* Ab0 = A  + (size_t)bm * lda + koff;
    const uint16_t* Bb0 = Bt + (size_t)bn * ldb + koff;

    auto loadStage = [&](int kt, int stage) {
        uint16_t* As = smb + stage * STAGE_ELEMS;
        uint16_t* Bs = As + ATILE;
        #pragma unroll
        for (int i = 0; i < 4; i++) {
            int idx = tid + i * 256;
            int r = idx >> 3, c = idx & 7;
            cp_async16(As + r * ASTR + c * 8, Ab0 + (size_t)r * lda + kt * BKT + c * 8);
            cp_async16(Bs + r * ASTR + c * 8, Bb0 + (size_t)r * ldb + kt * BKT + c * 8);
        }
        asm volatile("cp.async.commit_group;\n" ::);
    };

    float acc[2][8][4];
    #pragma unroll
    for (int i = 0; i < 2; i++)
        #pragma unroll
        for (int j = 0; j < 8; j++)
            #pragma unroll
            for (int q = 0; q < 4; q++) acc[i][j][q] = 0.f;

    const uint32_t smemBase = (uint32_t)__cvta_generic_to_shared(smb);
    const int arow = lane & 15, ahalf = lane >> 4;
    const uint32_t aoff0 = (uint32_t)(((wm      + arow) * ASTR + ahalf * 8) * 2);
    const uint32_t aoff1 = (uint32_t)(((wm + 16 + arow) * ASTR + ahalf * 8) * 2);
    uint32_t boff[4];
    #pragma unroll
    for (int p = 0; p < 4; p++)
        boff[p] = (uint32_t)(((wn + p * 16 + arow) * ASTR + ahalf * 8) * 2) + ATILE * 2;

    const int nk = K / BKT;
    loadStage(0, 0);

    for (int kt = 0; kt < nk; kt++) {
        if (kt + 1 < nk) {
            loadStage(kt + 1, (kt + 1) & 1);
            asm volatile("cp.async.wait_group 1;\n" ::);
        } else {
            asm volatile("cp.async.wait_group 0;\n" ::);
        }
        __syncthreads();

        const uint32_t st = smemBase + (kt & 1) * STAGE_BYTES;

        #pragma unroll
        for (int ks = 0; ks < 4; ks++) {
            const uint32_t kadd = ks * 32;
            uint32_t af[2][4], bw[4][4];
            LDSM_X4(af[0][0], af[0][1], af[0][2], af[0][3], st + aoff0 + kadd);
            LDSM_X4(af[1][0], af[1][1], af[1][2], af[1][3], st + aoff1 + kadd);
            #pragma unroll
            for (int p = 0; p < 4; p++)
                LDSM_X4(bw[p][0], bw[p][1], bw[p][2], bw[p][3], st + boff[p] + kadd);
            #pragma unroll
            for (int mt = 0; mt < 2; mt++)
                #pragma unroll
                for (int nt = 0; nt < 8; nt++) {
                    uint32_t b0 = bw[nt >> 1][nt & 1];
                    uint32_t b1 = bw[nt >> 1][2 + (nt & 1)];
                    asm volatile(
                        "mma.sync.aligned.m16n8k16.row.col.f32.bf16.bf16.f32 "
                        "{%0,%1,%2,%3}, {%4,%5,%6,%7}, {%8,%9}, {%0,%1,%2,%3};\n"
                        : "+f"(acc[mt][nt][0]), "+f"(acc[mt][nt][1]),
                          "+f"(acc[mt][nt][2]), "+f"(acc[mt][nt][3])
                        : "r"(af[mt][0]), "r"(af[mt][1]), "r"(af[mt][2]), "r"(af[mt][3]),
                          "r"(b0), "r"(b1));
                }
        }
        __syncthreads();
    }

    float* Cout = (epi == 3) ? (Cf + (size_t)blockIdx.z * M * N) : Cf;
    #pragma unroll
    for (int mt = 0; mt < 2; mt++) {
        #pragma unroll
        for (int nt = 0; nt < 8; nt++) {
            int c = bn + wn + nt * 8 + t * 2;
            float bx = 0.f, by = 0.f;
            if (epi != 3) { bx = bias[c]; by = bias[c + 1]; }
            #pragma unroll
            for (int rr = 0; rr < 2; rr++) {
                int gm = bm + wm + mt * 16 + g + rr * 8;
                size_t off = (size_t)gm * N + c;
                float vx = acc[mt][nt][rr * 2 + 0] + bx;
                float vy = acc[mt][nt][rr * 2 + 1] + by;
                if (epi == 1) {
                    *(uint32_t*)&Cb[off] = pack_bf2(gelu_tanh(vx), gelu_tanh(vy));
                } else if (epi == 2) {
                    *(uint32_t*)&Cb[off] = pack_bf2(vx, vy);
                } else {
                    *(float2*)&Cout[off] = make_float2(vx, vy);
                }
            }
        }
    }
}

// ---------------- causal attention (bf16 in, bf16 out) ----------------
__global__ void __launch_bounds__(256) attn_kernel(
        const uint16_t* __restrict__ qkv, uint16_t* __restrict__ o) {
    const int qt = blockIdx.x, hh = blockIdx.y, b = blockIdx.z;
    const int tid = threadIdx.x;
    const int ql = tid >> 2, part = tid & 3;
    const int q  = qt * 64 + ql;

    __shared__ float Ks[64 * 68];
    __shared__ float Vs[64 * 68];

    float qreg[16], acc[16];
    {
        const uint16_t* qp = qkv + (size_t)(b * TTOT + q) * (3 * DIM) + hh * HDIM + part * 16;
        uint4 u0 = ((const uint4*)qp)[0];
        uint4 u1 = ((const uint4*)qp)[1];
        uint32_t ws[8] = {u0.x, u0.y, u0.z, u0.w, u1.x, u1.y, u1.z, u1.w};
        #pragma unroll
        for (int i = 0; i < 8; i++) {
            float2 f = unpack_bf2(ws[i]);
            qreg[2*i] = f.x; qreg[2*i+1] = f.y;
        }
    }
    #pragma unroll
    for (int d = 0; d < 16; d++) acc[d] = 0.f;
    float mrun = -1e30f, lrun = 0.f;

    const int nkt = qt + 1;
    for (int kt = 0; kt < nkt; kt++) {
        {
            int r = tid >> 2, c = (tid & 3) * 16;
            const uint16_t* kp = qkv + (size_t)(b * TTOT + kt * 64 + r) * (3 * DIM)
                                 + DIM + hh * HDIM + c;
            const uint16_t* vp = kp + DIM;
            uint4 k0 = ((const uint4*)kp)[0], k1 = ((const uint4*)kp)[1];
            uint4 v0 = ((const uint4*)vp)[0], v1 = ((const uint4*)vp)[1];
            uint32_t kw[8] = {k0.x, k0.y, k0.z, k0.w, k1.x, k1.y, k1.z, k1.w};
            uint32_t vw[8] = {v0.x, v0.y, v0.z, v0.w, v1.x, v1.y, v1.z, v1.w};
            #pragma unroll
            for (int i = 0; i < 8; i++) {
                float2 kf = unpack_bf2(kw[i]);
                float2 vf = unpack_bf2(vw[i]);
                int cb = c + 2 * i;
                Ks[r * 68 + swz(cb)]     = kf.x;
                Ks[r * 68 + swz(cb + 1)] = kf.y;
                Vs[r * 68 + swz(cb)]     = vf.x;
                Vs[r * 68 + swz(cb + 1)] = vf.y;
            }
        }
        __syncthreads();

        const int pbase = part * 17;
        for (int j0 = 0; j0 < 64; j0 += 4) {
            float sj[4];
            #pragma unroll
            for (int jj = 0; jj < 4; jj++) {
                const float* kr = &Ks[(j0 + jj) * 68 + pbase];
                float s = 0.f;
                #pragma unroll
                for (int d = 0; d < 16; d++) s = fmaf(qreg[d], kr[d], s);
                s += __shfl_xor_sync(0xffffffffu, s, 1);
                s += __shfl_xor_sync(0xffffffffu, s, 2);
                s *= 0.125f;
                int kg = kt * 64 + j0 + jj;
                sj[jj] = (kg <= q) ? s : -1e30f;
            }
            float tmax = fmaxf(fmaxf(sj[0], sj[1]), fmaxf(sj[2], sj[3]));
            if (tmax > mrun) {
                float corr = __expf(mrun - tmax);
                lrun *= corr;
                #pragma unroll
                for (int d = 0; d < 16; d++) acc[d] *= corr;
                mrun = tmax;
            }
            float pm = __expf(sj[part] - mrun);
            float p0 = __shfl_sync(0xffffffffu, pm, 0, 4);
            float p1 = __shfl_sync(0xffffffffu, pm, 1, 4);
            float p2 = __shfl_sync(0xffffffffu, pm, 2, 4);
            float p3 = __shfl_sync(0xffffffffu, pm, 3, 4);
            lrun += p0 + p1 + p2 + p3;
            const float* vr0 = &Vs[(j0 + 0) * 68 + pbase];
            const float* vr1 = &Vs[(j0 + 1) * 68 + pbase];
            const float* vr2 = &Vs[(j0 + 2) * 68 + pbase];
            const float* vr3 = &Vs[(j0 + 3) * 68 + pbase];
            #pragma unroll
            for (int d = 0; d < 16; d++) {
                float a = acc[d];
                a = fmaf(p0, vr0[d], a);
                a = fmaf(p1, vr1[d], a);
                a = fmaf(p2, vr2[d], a);
                a = fmaf(p3, vr3[d], a);
                acc[d] = a;
            }
        }
        __syncthreads();
    }

    float inv = 1.0f / lrun;
    uint16_t* op = o + (size_t)(b * TTOT + q) * DIM + hh * HDIM + part * 16;
    uint4 u0, u1;
    u0.x = pack_bf2(acc[0]*inv,  acc[1]*inv);  u0.y = pack_bf2(acc[2]*inv,  acc[3]*inv);
    u0.z = pack_bf2(acc[4]*inv,  acc[5]*inv);  u0.w = pack_bf2(acc[6]*inv,  acc[7]*inv);
    u1.x = pack_bf2(acc[8]*inv,  acc[9]*inv);  u1.y = pack_bf2(acc[10]*inv, acc[11]*inv);
    u1.z = pack_bf2(acc[12]*inv, acc[13]*inv); u1.w = pack_bf2(acc[14]*inv, acc[15]*inv);
    ((uint4*)op)[0] = u0;
    ((uint4*)op)[1] = u1;
}

// ---------------- finalize ----------------
__global__ void __launch_bounds__(256) finalize_kernel(
        const float* __restrict__ h, const float* __restrict__ noise,
        const float* __restrict__ ong, const float* __restrict__ onb,
        const float* __restrict__ Weos, const float* __restrict__ beos,
        float* __restrict__ last, float* __restrict__ cur,
        float* __restrict__ out, int out_size) {
    int b = blockIdx.x, tid = threadIdx.x;
    float4 v = ((const float4*)(h + (size_t)(b * TTOT + TTOT - 1) * DIM))[tid];
    float s  = v.x + v.y + v.z + v.w;
    float ss = v.x*v.x + v.y*v.y + v.z*v.z + v.w*v.w;
    #pragma unroll
    for (int o = 16; o; o >>= 1) {
        s  += __shfl_xor_sync(0xffffffffu, s,  o);
        ss += __shfl_xor_sync(0xffffffffu, ss, o);
    }
    __shared__ float sh[16];
    int w = tid >> 5, l = tid & 31;
    if (l == 0) { sh[w] = s; sh[8 + w] = ss; }
    __syncthreads();
    float S = 0.f, SS = 0.f;
    #pragma unroll
    for (int i = 0; i < 8; i++) { S += sh[i]; SS += sh[8 + i]; }
    float mean = S * (1.0f / DIM);
    float var  = SS * (1.0f / DIM) - mean * mean;
    float rs   = rsqrtf(var + 1e-5f);
    float4 gg = ((const float4*)ong)[tid];
    float4 bb = ((const float4*)onb)[tid];
    float4 nv;
    nv.x = (v.x - mean) * rs * gg.x + bb.x;
    nv.y = (v.y - mean) * rs * gg.y + bb.y;
    nv.z = (v.z - mean) * rs * gg.z + bb.z;
    nv.w = (v.w - mean) * rs * gg.w + bb.w;
    ((float4*)(last + (size_t)b * DIM))[tid] = nv;
    float4 we = ((const float4*)Weos)[tid];
    float p = nv.x*we.x + nv.y*we.y + nv.z*we.z + nv.w*we.w;
    __shared__ float red[256];
    red[tid] = p;
    __syncthreads();
    for (int st = 128; st; st >>= 1) {
        if (tid < st) red[tid] += red[tid + st];
        __syncthreads();
    }
    if (tid == 0 && (1024 + b) < out_size) {
        float e = red[0] + beos[0];
        out[1024 + b] = (e > 0.5f) ? 1.0f : 0.0f;
    }
    if (tid < LDIMC) cur[b * LDIMC + tid] = noise[b * LDIMC + tid];
}

// ---------------- persistent flow decoder ----------------
#define FLOW_BLOCKS 128
#define FLOW_SMEM ((8*KP1 + 8*HID)*4)

__device__ __forceinline__ void gbar(unsigned expect) {
    __syncthreads();
    if (threadIdx.x == 0) {
        __threadfence();
        unsigned a = atomicAdd(&g_bar_cnt, 1u);
        if (a == FLOW_BLOCKS - 1) {
            atomicExch(&g_bar_cnt, 0u);
            __threadfence();
            atomicAdd(&g_bar_gen, 1u);
        } else {
            while (*((volatile unsigned*)&g_bar_gen) != expect) { }
            __threadfence();
        }
    }
    __syncthreads();
}

__global__ void __launch_bounds__(256) flow_all_kernel(
        const float* __restrict__ last, float* __restrict__ cur,
        const float* __restrict__ Wf1t, const float* __restrict__ bf1,
        const float* __restrict__ Wf2t, const float* __restrict__ bf2,
        const float* __restrict__ Wf3t, const float* __restrict__ bf3,
        float* __restrict__ f1, float* __restrict__ f2) {
    extern __shared__ float shf[];
    float* xs1 = shf;
    float* xs2 = shf + 8 * KP1;
    const int tid = threadIdx.x, blk = blockIdx.x;
    const int warp = tid >> 5, lane = tid & 31;

    unsigned gen0 = *((volatile unsigned*)&g_bar_gen);
    unsigned bc = 0;

    for (int i = tid; i < 8 * 1024; i += 256) {
        int m = i >> 10, k = i & 1023;
        xs1[m * KP1 + k] = last[m * 1024 + k];
    }
    if (tid < 48) {
        int m = tid / 6, k = KF1 + tid % 6;
        xs1[m * KP1 + k] = 0.f;
    }

    for (int step = 0; step < NSTEPS; step++) {
        float sv = (float)step / NSTEPS;
        float tv = (float)(step + 1) / NSTEPS;
        for (int i = tid; i < 8 * LDIMC; i += 256) {
            int m = i >> 7, k = i & 127;
            xs1[m * KP1 + 1026 + k] = cur[i];
        }
        if (tid < 16) {
            int m = tid >> 1;
            xs1[m * KP1 + 1024 + (tid & 1)] = (tid & 1) ? tv : sv;
        }
        __syncthreads();

        {
            int n = blk * 8 + warp;
            const float* wp = Wf1t + (size_t)n * KP1;
            float acc[8] = {0,0,0,0,0,0,0,0};
            for (int k0 = lane * 4; k0 < KP1; k0 += 128) {
                float4 w4 = *(const float4*)&wp[k0];
                #pragma unroll
                for (int m = 0; m < 8; m++) {
                    float4 x4 = *(const float4*)&xs1[m * KP1 + k0];
                    acc[m] += w4.x*x4.x + w4.y*x4.y + w4.z*x4.z + w4.w*x4.w;
                }
            }
            #pragma unroll
            for (int m = 0; m < 8; m++) {
                float v = acc[m];
                #pragma unroll
                for (int o2 = 16; o2; o2 >>= 1) v += __shfl_xor_sync(0xffffffffu, v, o2);
                acc[m] = v;
            }
            if (lane == 0) {
                float bn = bf1[n];
                #pragma unroll
                for (int m = 0; m < 8; m++) f1[m * HID + n] = silu(acc[m] + bn);
            }
        }
        gbar(gen0 + ++bc);

        for (int i = tid * 4; i < 8 * HID; i += 1024)
            *(float4*)&xs2[i] = *(const float4*)&f1[i];
        __syncthreads();
        {
            int n = blk * 8 + warp;
            const float* wp = Wf2t + (size_t)n * HID;
            float acc[8] = {0,0,0,0,0,0,0,0};
            for (int k0 = lane * 4; k0 < HID; k0 += 128) {
                float4 w4 = *(const float4*)&wp[k0];
                #pragma unroll
                for (int m = 0; m < 8; m++) {
                    float4 x4 = *(const float4*)&xs2[m * HID + k0];
                    acc[m] += w4.x*x4.x + w4.y*x4.y + w4.z*x4.z + w4.w*x4.w;
                }
            }
            #pragma unroll
            for (int m = 0; m < 8; m++) {
                float v = acc[m];
                #pragma unroll
                for (int o2 = 16; o2; o2 >>= 1) v += __shfl_xor_sync(0xffffffffu, v, o2);
                acc[m] = v;
            }
            if (lane == 0) {
                float bn = bf2[n];
                #pragma unroll
                for (int m = 0; m < 8; m++) f2[m * HID + n] = silu(acc[m] + bn);
            }
        }
        gbar(gen0 + ++bc);

        if (blk < 16) {
            for (int i = tid * 4; i < 8 * HID; i += 1024)
                *(float4*)&xs2[i] = *(const float4*)&f2[i];
            __syncthreads();
            int n = blk * 8 + warp;
            const float* wp = Wf3t + (size_t)n * HID;
            float acc[8] = {0,0,0,0,0,0,0,0};
            for (int k0 = lane * 4; k0 < HID; k0 += 128) {
                float4 w4 = *(const float4*)&wp[k0];
                #pragma unroll
                for (int m = 0; m < 8; m++) {
                    float4 x4 = *(const float4*)&xs2[m * HID + k0];
                    acc[m] += w4.x*x4.x + w4.y*x4.y + w4.z*x4.z + w4.w*x4.w;
                }
            }
            #pragma unroll
            for (int m = 0; m < 8; m++) {
                float v = acc[m];
                #pragma unroll
                for (int o2 = 16; o2; o2 >>= 1) v += __shfl_xor_sync(0xffffffffu, v, o2);
                acc[m] = v;
            }
            if (lane == 0) {
                float bn = bf3[n];
                #pragma unroll
                for (int m = 0; m < 8; m++)
                    cur[m * LDIMC + n] += (acc[m] + bn) * (1.0f / NSTEPS);
            }
        }
        gbar(gen0 + ++bc);
    }
}

__global__ void writeout_kernel(const float* __restrict__ cur,
                                float* __restrict__ out, int out_size) {
    int i = blockIdx.x * blockDim.x + threadIdx.x;
    if (i >= out_size) return;
    if (i < 1024)       out[i] = cur[i];
    else if (i >= 1032) out[i] = 0.0f;
}

// ---------------- host orchestration ----------------
extern "C" void kernel_launch(void* const* d_in, const int* in_sizes, int n_in,
                              void* d_out, int out_size) {
    const float* seq   = (const float*)d_in[0];
    const float* text  = (const float*)d_in[1];
    const float* noise = (const float*)d_in[2];
    const float* bos   = (const float*)d_in[4];
    const float* W_in  = (const float*)d_in[5];
    const float* b_in  = (const float*)d_in[6];
    const float* ln1g  = (const float*)d_in[7];
    const float* ln1b  = (const float*)d_in[8];
    const float* Wqkv  = (const float*)d_in[9];
    const float* bqkv  = (const float*)d_in[10];
    const float* Wo    = (const float*)d_in[11];
    const float* bo    = (const float*)d_in[12];
    const float* ln2g  = (const float*)d_in[13];
    const float* ln2b  = (const float*)d_in[14];
    const float* W1    = (const float*)d_in[15];
    const float* b1    = (const float*)d_in[16];
    const float* W2    = (const float*)d_in[17];
    const float* b2    = (const float*)d_in[18];
    const float* ong   = (const float*)d_in[19];
    const float* onb   = (const float*)d_in[20];
    const float* Weos  = (const float*)d_in[21];
    const float* beos  = (const float*)d_in[22];
    const float* Wf1   = (const float*)d_in[23];
    const float* bf1   = (const float*)d_in[24];
    const float* Wf2   = (const float*)d_in[25];
    const float* bf2   = (const float*)d_in[26];
    const float* Wf3   = (const float*)d_in[27];
    const float* bf3   = (const float*)d_in[28];
    float* out = (float*)d_out;

    uint16_t *p_seqb, *p_tmpb, *p_qkvb, *p_attb, *p_midb;
    uint16_t *p_wint, *p_wqkvt, *p_wot, *p_w1t, *p_w2t;
    float *p_x, *p_h, *p_last, *p_cur, *p_f1, *p_f2, *p_p01;
    float *p_wf1t, *p_wf2t, *p_wf3t;
    cudaGetSymbolAddress((void**)&p_seqb,  g_seqb);
    cudaGetSymbolAddress((void**)&p_tmpb,  g_tmpb);
    cudaGetSymbolAddress((void**)&p_qkvb,  g_qkvb);
    cudaGetSymbolAddress((void**)&p_attb,  g_attb);
    cudaGetSymbolAddress((void**)&p_midb,  g_midb);
    cudaGetSymbolAddress((void**)&p_wint,  g_wint);
    cudaGetSymbolAddress((void**)&p_wqkvt, g_wqkvt);
    cudaGetSymbolAddress((void**)&p_wot,   g_wot);
    cudaGetSymbolAddress((void**)&p_w1t,   g_w1t);
    cudaGetSymbolAddress((void**)&p_w2t,   g_w2t);
    cudaGetSymbolAddress((void**)&p_x,     g_x);
    cudaGetSymbolAddress((void**)&p_h,     g_h);
    cudaGetSymbolAddress((void**)&p_last,  g_last);
    cudaGetSymbolAddress((void**)&p_cur,   g_cur);
    cudaGetSymbolAddress((void**)&p_f1,    g_f1);
    cudaGetSymbolAddress((void**)&p_f2,    g_f2);
    cudaGetSymbolAddress((void**)&p_p01,   g_p01);
    cudaGetSymbolAddress((void**)&p_wf1t,  g_wf1t);
    cudaGetSymbolAddress((void**)&p_wf2t,  g_wf2t);
    cudaGetSymbolAddress((void**)&p_wf3t,  g_wf3t);

    cudaFuncSetAttribute(tgemm_bf16,
                         cudaFuncAttributeMaxDynamicSharedMemorySize, TG_SMEM);
    cudaFuncSetAttribute(flow_all_kernel,
                         cudaFuncAttributeMaxDynamicSharedMemorySize, FLOW_SMEM);

    dim3 tb(32, 8);
    int nseq = BDIM * TSEQ * LDIMC;

    tconv_kernel<<<dim3(DIM/32,  LDIMC/64, 1),      tb>>>(W_in, p_wint,  LDIMC, DIM);
    nanfix_kernel<<<(nseq + 255)/256, 256>>>(seq, bos, p_seqb, nseq);
    tconv_kernel<<<dim3(3*DIM/32, DIM/64, NLAYER),  tb>>>(Wqkv, p_wqkvt, DIM, 3*DIM);
    tgemm_bf16<<<dim3(DIM/128, (BDIM*TSEQ)/128, 1), 256, TG_SMEM>>>(
        p_seqb, LDIMC, p_wint, LDIMC, b_in, p_x, nullptr, BDIM*TSEQ, DIM, LDIMC, 0);
    concat_ln_kernel<<<MROWS, 256>>>(text, p_x, p_h, p_tmpb, ln1g, ln1b);
    tgemm_bf16<<<dim3(3*DIM/128, MROWS/128, 1), 256, TG_SMEM>>>(
        p_tmpb, DIM, p_wqkvt, DIM, bqkv, nullptr, p_qkvb, MROWS, 3*DIM, DIM, 2);

    // remaining weight prep
    tconv_kernel<<<dim3(DIM/32,  DIM/64, NLAYER),   tb>>>(Wo,   p_wot,   DIM, DIM);
    tconv_kernel<<<dim3(FFN/32,  DIM/64, NLAYER),   tb>>>(W1,   p_w1t,   DIM, FFN);
    tconv_kernel<<<dim3(DIM/32,  FFN/64, NLAYER),   tb>>>(W2,   p_w2t,   FFN, DIM);
    zero_kernel<<<(HID*KP1 + 255)/256, 256>>>(p_wf1t, HID*KP1);
    transpose_kernel<<<dim3((HID+31)/32, (KF1+31)/32), tb>>>(Wf1, p_wf1t, KF1, HID, KP1);
    transpose_kernel<<<dim3((HID+31)/32, (HID+31)/32), tb>>>(Wf2, p_wf2t, HID, HID, HID);
    transpose_kernel<<<dim3((LDIMC+31)/32, (HID+31)/32), tb>>>(Wf3, p_wf3t, HID, LDIMC, HID);

    // transformer layers (QKV for layer l+1 launched at end of layer l)
    for (int l = 0; l < NLAYER; l++) {
        attn_kernel<<<dim3(TTOT/64, HEADS, BDIM), 256>>>(p_qkvb, p_attb);
        tgemm_bf16<<<dim3(DIM/128, MROWS/128, KSLICES), 256, TG_SMEM>>>(
            p_attb, DIM, p_wot + (size_t)l*DIM*DIM, DIM,
            nullptr, p_p01, nullptr, MROWS, DIM, 1024/KSLICES, 3);
        combine_ln_kernel<<<MROWS, 256>>>(
            p_p01, bo + l*DIM, p_h,
            ln2g + l*DIM, ln2b + l*DIM, p_tmpb, 1);
        tgemm_bf16<<<dim3(FFN/128, MROWS/128, 1), 256, TG_SMEM>>>(
            p_tmpb, DIM, p_w1t + (size_t)l*FFN*DIM, DIM,
            b1 + l*FFN, nullptr, p_midb, MROWS, FFN, DIM, 1);
        tgemm_bf16<<<dim3(DIM/128, MROWS/128, KSLICES), 256, TG_SMEM>>>(
            p_midb, FFN, p_w2t + (size_t)l*DIM*FFN, FFN,
            nullptr, p_p01, nullptr, MROWS, DIM, 4096/KSLICES, 3);
        if (l < NLAYER - 1) {
            combine_ln_kernel<<<MROWS, 256>>>(
                p_p01, b2 + l*DIM, p_h,
                ln1g + (l+1)*DIM, ln1b + (l+1)*DIM, p_tmpb, 1);
            tgemm_bf16<<<dim3(3*DIM/128, MROWS/128, 1), 256, TG_SMEM>>>(
                p_tmpb, DIM, p_wqkvt + (size_t)(l+1)*3*DIM*DIM, DIM,
                bqkv + (l+1)*3*DIM, nullptr, p_qkvb, MROWS, 3*DIM, DIM, 2);
        } else {
            combine_ln_kernel<<<MROWS, 256>>>(
                p_p01, b2 + l*DIM, p_h,
                nullptr, nullptr, nullptr, 0);
        }
    }

    // finalize
    finalize_kernel<<<BDIM, 256>>>(p_h, noise, ong, onb, Weos, beos,
                                   p_last, p_cur, out, out_size);

    // persistent flow decoder
    flow_all_kernel<<<FLOW_BLOCKS, 256, FLOW_SMEM>>>(
        p_last, p_cur, p_wf1t, bf1, p_wf2t, bf2, p_wf3t, bf3, p_f1, p_f2);

    // write output
    int ncov = out_size > 1024 ? out_size : 1024;
    writeout_kernel<<<(ncov + 255)/256, 256>>>(p_cur, out, out_size);
}